// round 1
// baseline (speedup 1.0000x reference)
#include <cuda_runtime.h>
#include <math.h>

// Problem constants
#define B_    4
#define TQ_   1024
#define TKV_  1024
#define D_    1024
#define H_    16
#define HD_   64
#define EPS_  1e-5f

// ---------------------------------------------------------------------------
// Device scratch (globals — allocation-free per harness rules)
// ---------------------------------------------------------------------------
__device__ float g_qproj [B_ * TQ_  * 2 * D_];   //  33.5 MB (B,TQ,2D)
__device__ float g_kvproj[B_ * TKV_ * 3 * D_];   //  50.3 MB (B,TKV,3D)
__device__ float g_q1n   [B_ * H_ * TQ_  * HD_]; //  16.8 MB (B,H,TQ,HD)
__device__ float g_q2n   [B_ * H_ * TQ_  * HD_];
__device__ float g_k1n   [B_ * H_ * TKV_ * HD_];
__device__ float g_k2n   [B_ * H_ * TKV_ * HD_];
__device__ float g_vh    [B_ * H_ * TKV_ * HD_];
__device__ float g_y     [B_ * H_ * TQ_  * HD_]; // attention output (B,H,TQ,HD)
__device__ float g_ybt   [B_ * TQ_ * D_];        // groupnormed, (B,TQ,D)
__device__ float g_stats [B_ * H_ * 2];          // mu, rstd per (b,h)

// ---------------------------------------------------------------------------
// SGEMM: C[M,N] = A[M,K] @ B[K,N], all row-major fp32. 128x128x16 tile,
// 256 threads, 8x8 micro-tile (2x2 of 4x4 for vectorized frag loads).
// ---------------------------------------------------------------------------
__global__ __launch_bounds__(256) void sgemm128(
    const float* __restrict__ A, const float* __restrict__ Bm,
    float* __restrict__ C, int M, int N, int K)
{
    __shared__ float As[16][128];
    __shared__ float Bs[16][128];

    const int tid = threadIdx.x;
    const int bx = blockIdx.x;   // N tile
    const int by = blockIdx.y;   // M tile

    // A tile loaders: 128 rows x 16 k; each thread: rows aRow, aRow+64, 4 floats of k
    const int aRow = tid >> 2;            // 0..63
    const int aCol = (tid & 3) << 2;      // 0,4,8,12
    // B tile loaders: 16 k x 128 n; each thread: rows bRow, bRow+8, float4 of n
    const int bRow = tid >> 5;            // 0..7
    const int bCol = (tid & 31) << 2;     // 0..124

    const int tr = (tid >> 4) << 2;       // 0..60 step 4
    const int tc = (tid & 15) << 2;       // 0..60 step 4

    const float* Ab = A  + (size_t)(by * 128) * K;
    const float* Bb = Bm + bx * 128;

    float acc[8][8];
    #pragma unroll
    for (int i = 0; i < 8; i++)
        #pragma unroll
        for (int j = 0; j < 8; j++) acc[i][j] = 0.f;

    for (int k0 = 0; k0 < K; k0 += 16) {
        float4 a0 = *(const float4*)&Ab[(size_t)aRow        * K + k0 + aCol];
        float4 a1 = *(const float4*)&Ab[(size_t)(aRow + 64) * K + k0 + aCol];
        float4 b0 = *(const float4*)&Bb[(size_t)(k0 + bRow)     * N + bCol];
        float4 b1 = *(const float4*)&Bb[(size_t)(k0 + bRow + 8) * N + bCol];

        As[aCol + 0][aRow]      = a0.x;
        As[aCol + 1][aRow]      = a0.y;
        As[aCol + 2][aRow]      = a0.z;
        As[aCol + 3][aRow]      = a0.w;
        As[aCol + 0][aRow + 64] = a1.x;
        As[aCol + 1][aRow + 64] = a1.y;
        As[aCol + 2][aRow + 64] = a1.z;
        As[aCol + 3][aRow + 64] = a1.w;
        *(float4*)&Bs[bRow][bCol]     = b0;
        *(float4*)&Bs[bRow + 8][bCol] = b1;
        __syncthreads();

        #pragma unroll
        for (int kk = 0; kk < 16; kk++) {
            float af[8], bf[8];
            *(float4*)&af[0] = *(const float4*)&As[kk][tr];
            *(float4*)&af[4] = *(const float4*)&As[kk][tr + 64];
            *(float4*)&bf[0] = *(const float4*)&Bs[kk][tc];
            *(float4*)&bf[4] = *(const float4*)&Bs[kk][tc + 64];
            #pragma unroll
            for (int i = 0; i < 8; i++)
                #pragma unroll
                for (int j = 0; j < 8; j++)
                    acc[i][j] += af[i] * bf[j];
        }
        __syncthreads();
    }

    #pragma unroll
    for (int ih = 0; ih < 2; ih++)
        #pragma unroll
        for (int i = 0; i < 4; i++) {
            const int row = by * 128 + ih * 64 + tr + i;
            #pragma unroll
            for (int jh = 0; jh < 2; jh++) {
                const int col = bx * 128 + jh * 64 + tc;
                float4 o;
                o.x = acc[ih * 4 + i][jh * 4 + 0];
                o.y = acc[ih * 4 + i][jh * 4 + 1];
                o.z = acc[ih * 4 + i][jh * 4 + 2];
                o.w = acc[ih * 4 + i][jh * 4 + 3];
                *(float4*)&C[(size_t)row * N + col] = o;
            }
        }
}

// ---------------------------------------------------------------------------
// RMSNorm + head split for Q: qproj (B*TQ, 2D) -> q1n/q2n (B,H,TQ,HD)
// one warp per (row, head, which)
// ---------------------------------------------------------------------------
__global__ void rms_q_kernel(const float* __restrict__ qp,
                             const float* __restrict__ qn1, const float* __restrict__ qn2,
                             float* __restrict__ q1n, float* __restrict__ q2n)
{
    const int gw   = (blockIdx.x * blockDim.x + threadIdx.x) >> 5;
    const int lane = threadIdx.x & 31;
    // gw = (row*16 + h)*2 + which
    const int which = gw & 1;
    const int h     = (gw >> 1) & 15;
    const int row   = gw >> 5;
    const float* src = qp + (size_t)row * 2048 + which * 1024 + h * 64 + lane * 2;
    float2 v = *(const float2*)src;
    float ss = v.x * v.x + v.y * v.y;
    #pragma unroll
    for (int o = 16; o; o >>= 1) ss += __shfl_xor_sync(0xffffffffu, ss, o);
    const float r = rsqrtf(ss * (1.0f / 64.0f) + EPS_);
    const int b = row >> 10, t = row & 1023;
    const float* w = (which ? qn2 : qn1) + lane * 2;
    float* dst = (which ? q2n : q1n)
               + (((size_t)b * 16 + h) * 1024 + t) * 64 + lane * 2;
    float2 o2;
    o2.x = v.x * r * w[0];
    o2.y = v.y * r * w[1];
    *(float2*)dst = o2;
}

// ---------------------------------------------------------------------------
// RMSNorm + head split for KV: kvproj (B*TKV, 3D) -> k1n/k2n/vh (B,H,TKV,HD)
// which: 0=k1(norm), 1=k2(norm), 2=v(copy)
// ---------------------------------------------------------------------------
__global__ void rms_kv_kernel(const float* __restrict__ kvp,
                              const float* __restrict__ kn1, const float* __restrict__ kn2,
                              float* __restrict__ k1n, float* __restrict__ k2n,
                              float* __restrict__ vh)
{
    const int gw   = (blockIdx.x * blockDim.x + threadIdx.x) >> 5;
    const int lane = threadIdx.x & 31;
    // gw = (row*16 + h)*3 + which
    const int which = gw % 3;
    const int rh    = gw / 3;
    const int h     = rh & 15;
    const int row   = rh >> 4;
    const float* src = kvp + (size_t)row * 3072 + which * 1024 + h * 64 + lane * 2;
    float2 v = *(const float2*)src;
    float r = 1.0f;
    float w0 = 1.0f, w1 = 1.0f;
    if (which < 2) {
        float ss = v.x * v.x + v.y * v.y;
        #pragma unroll
        for (int o = 16; o; o >>= 1) ss += __shfl_xor_sync(0xffffffffu, ss, o);
        r = rsqrtf(ss * (1.0f / 64.0f) + EPS_);
        const float* w = (which ? kn2 : kn1) + lane * 2;
        w0 = w[0]; w1 = w[1];
    }
    const int b = row >> 10, t = row & 1023;
    float* dst = (which == 0 ? k1n : (which == 1 ? k2n : vh))
               + (((size_t)b * 16 + h) * 1024 + t) * 64 + lane * 2;
    float2 o2;
    o2.x = v.x * r * w0;
    o2.y = v.y * r * w1;
    *(float2*)dst = o2;
}

// ---------------------------------------------------------------------------
// Fused dual flash attention:
//   y = softmax(q1 k1^T/8) v - softplus(lmb) * softmax(q2 k2^T/8) v
// block = (q tile of 64 rows, h, b); 256 threads; online softmax over 16 kv tiles.
// ---------------------------------------------------------------------------
#define SSTR 68   // 64 + 4 pad (keeps float4 alignment, reduces bank conflicts)

__device__ __forceinline__ void compute_S(const float* sQ, const float* sK,
                                          float* sS, int tr, int tc)
{
    float s[4][4];
    #pragma unroll
    for (int i = 0; i < 4; i++)
        #pragma unroll
        for (int j = 0; j < 4; j++) s[i][j] = 0.f;

    #pragma unroll
    for (int d4 = 0; d4 < 16; d4++) {
        float4 q[4], k[4];
        #pragma unroll
        for (int i = 0; i < 4; i++)
            q[i] = *(const float4*)&sQ[(tr + 16 * i) * SSTR + d4 * 4];
        #pragma unroll
        for (int j = 0; j < 4; j++)
            k[j] = *(const float4*)&sK[(tc + 16 * j) * SSTR + d4 * 4];
        #pragma unroll
        for (int i = 0; i < 4; i++)
            #pragma unroll
            for (int j = 0; j < 4; j++)
                s[i][j] += q[i].x * k[j].x + q[i].y * k[j].y
                         + q[i].z * k[j].z + q[i].w * k[j].w;
    }
    #pragma unroll
    for (int i = 0; i < 4; i++)
        #pragma unroll
        for (int j = 0; j < 4; j++)
            sS[(tr + 16 * i) * SSTR + tc + 16 * j] = s[i][j];
}

__device__ __forceinline__ void softmax_update(float* sS, float* smv, float* slv,
                                               float* sal, int tid)
{
    const int row = tid >> 2, part = tid & 3;
    float* p = &sS[row * SSTR + part * 16];
    float mx = -1e30f;
    #pragma unroll
    for (int i = 0; i < 16; i++) mx = fmaxf(mx, p[i]);
    mx = fmaxf(mx, __shfl_xor_sync(0xffffffffu, mx, 1));
    mx = fmaxf(mx, __shfl_xor_sync(0xffffffffu, mx, 2));
    const float mold = smv[row];
    const float mnew = fmaxf(mold, mx);
    const float alpha = __expf(mold - mnew);
    float ps = 0.f;
    #pragma unroll
    for (int i = 0; i < 16; i++) {
        float e = __expf(p[i] - mnew);
        p[i] = e;
        ps += e;
    }
    ps += __shfl_xor_sync(0xffffffffu, ps, 1);
    ps += __shfl_xor_sync(0xffffffffu, ps, 2);
    if (part == 0) {
        smv[row] = mnew;
        slv[row] = slv[row] * alpha + ps;
        sal[row] = alpha;
    }
}

__device__ __forceinline__ void pv_accum(float acc[4][4], const float* sS,
                                         const float* sV, const float* sal,
                                         int tr, int tc)
{
    #pragma unroll
    for (int i = 0; i < 4; i++) {
        const float a = sal[tr + 16 * i];
        #pragma unroll
        for (int k = 0; k < 4; k++) acc[i][k] *= a;
    }
    #pragma unroll
    for (int j4 = 0; j4 < 16; j4++) {
        float4 pr[4];
        #pragma unroll
        for (int i = 0; i < 4; i++)
            pr[i] = *(const float4*)&sS[(tr + 16 * i) * SSTR + j4 * 4];
        float4 v4[4];
        #pragma unroll
        for (int jj = 0; jj < 4; jj++)
            v4[jj] = *(const float4*)&sV[(j4 * 4 + jj) * SSTR + tc * 4];
        #pragma unroll
        for (int i = 0; i < 4; i++) {
            const float* pf = (const float*)&pr[i];
            #pragma unroll
            for (int jj = 0; jj < 4; jj++) {
                acc[i][0] += pf[jj] * v4[jj].x;
                acc[i][1] += pf[jj] * v4[jj].y;
                acc[i][2] += pf[jj] * v4[jj].z;
                acc[i][3] += pf[jj] * v4[jj].w;
            }
        }
    }
}

#define FLASH_SMEM ((6 * 64 * SSTR + 5 * 64) * (int)sizeof(float))

__global__ __launch_bounds__(256) void flash_kernel(
    const float* __restrict__ q1n, const float* __restrict__ q2n,
    const float* __restrict__ k1n, const float* __restrict__ k2n,
    const float* __restrict__ vh,  const float* __restrict__ lmb,
    float* __restrict__ y)
{
    extern __shared__ float smbuf[];
    float* sQ1 = smbuf;
    float* sQ2 = sQ1 + 64 * SSTR;
    float* sK1 = sQ2 + 64 * SSTR;
    float* sK2 = sK1 + 64 * SSTR;
    float* sV  = sK2 + 64 * SSTR;
    float* sS  = sV  + 64 * SSTR;
    float* sm1 = sS  + 64 * SSTR;
    float* sl1 = sm1 + 64;
    float* sm2 = sl1 + 64;
    float* sl2 = sm2 + 64;
    float* sal = sl2 + 64;

    const int tid = threadIdx.x;
    const int qt = blockIdx.x, h = blockIdx.y, b = blockIdx.z;
    const int bh = b * H_ + h;
    const size_t qbase  = ((size_t)bh * TQ_ + qt * 64) * HD_;
    const size_t kvbase = (size_t)bh * TKV_ * HD_;

    // Load Q tiles (prescaled by 1/sqrt(HD) = 1/8)
    for (int i = tid; i < 64 * 16; i += 256) {
        const int r = i >> 4, c4 = (i & 15) << 2;
        float4 a = *(const float4*)&q1n[qbase + (size_t)r * HD_ + c4];
        a.x *= 0.125f; a.y *= 0.125f; a.z *= 0.125f; a.w *= 0.125f;
        *(float4*)&sQ1[r * SSTR + c4] = a;
        float4 bq = *(const float4*)&q2n[qbase + (size_t)r * HD_ + c4];
        bq.x *= 0.125f; bq.y *= 0.125f; bq.z *= 0.125f; bq.w *= 0.125f;
        *(float4*)&sQ2[r * SSTR + c4] = bq;
    }
    if (tid < 64) {
        sm1[tid] = -1e30f; sl1[tid] = 0.f;
        sm2[tid] = -1e30f; sl2[tid] = 0.f;
    }

    float acc1[4][4], acc2[4][4];
    #pragma unroll
    for (int i = 0; i < 4; i++)
        #pragma unroll
        for (int k = 0; k < 4; k++) { acc1[i][k] = 0.f; acc2[i][k] = 0.f; }

    const int tr = tid & 15;   // S-row group / P-row group
    const int tc = tid >> 4;   // S-col group / O-dim group

    for (int kt = 0; kt < TKV_ / 64; kt++) {
        __syncthreads();
        const size_t koff = kvbase + (size_t)kt * 64 * HD_;
        for (int i = tid; i < 64 * 16; i += 256) {
            const int r = i >> 4, c4 = (i & 15) << 2;
            *(float4*)&sK1[r * SSTR + c4] = *(const float4*)&k1n[koff + (size_t)r * HD_ + c4];
            *(float4*)&sK2[r * SSTR + c4] = *(const float4*)&k2n[koff + (size_t)r * HD_ + c4];
            *(float4*)&sV [r * SSTR + c4] = *(const float4*)&vh [koff + (size_t)r * HD_ + c4];
        }
        __syncthreads();
        // attention 1
        compute_S(sQ1, sK1, sS, tr, tc);
        __syncthreads();
        softmax_update(sS, sm1, sl1, sal, tid);
        __syncthreads();
        pv_accum(acc1, sS, sV, sal, tr, tc);
        __syncthreads();
        // attention 2
        compute_S(sQ2, sK2, sS, tr, tc);
        __syncthreads();
        softmax_update(sS, sm2, sl2, sal, tid);
        __syncthreads();
        pv_accum(acc2, sS, sV, sal, tr, tc);
    }
    __syncthreads();

    const float cmul = log1pf(__expf(lmb[h]));
    #pragma unroll
    for (int i = 0; i < 4; i++) {
        const int r = tr + 16 * i;
        const float il1 = 1.f / sl1[r];
        const float il2 = cmul / sl2[r];
        float4 o;
        o.x = acc1[i][0] * il1 - acc2[i][0] * il2;
        o.y = acc1[i][1] * il1 - acc2[i][1] * il2;
        o.z = acc1[i][2] * il1 - acc2[i][2] * il2;
        o.w = acc1[i][3] * il1 - acc2[i][3] * il2;
        *(float4*)&y[qbase + (size_t)r * HD_ + tc * 4] = o;
    }
}

// ---------------------------------------------------------------------------
// GroupNorm stats: per (b,h) mean/var over (TQ,HD) = 65536 elements
// ---------------------------------------------------------------------------
__global__ void gn_stats_kernel(const float* __restrict__ y, float* __restrict__ stats)
{
    __shared__ float rs[256], rq[256];
    const int bh = blockIdx.x, tid = threadIdx.x;
    const float* p = y + (size_t)bh * TQ_ * HD_;
    float s = 0.f, q = 0.f;
    for (int i = tid * 4; i < TQ_ * HD_; i += 256 * 4) {
        float4 v = *(const float4*)(p + i);
        s += v.x + v.y + v.z + v.w;
        q += v.x * v.x + v.y * v.y + v.z * v.z + v.w * v.w;
    }
    rs[tid] = s; rq[tid] = q;
    __syncthreads();
    for (int o = 128; o; o >>= 1) {
        if (tid < o) { rs[tid] += rs[tid + o]; rq[tid] += rq[tid + o]; }
        __syncthreads();
    }
    if (tid == 0) {
        const float inv = 1.f / (float)(TQ_ * HD_);
        const float mu = rs[0] * inv;
        const float var = rq[0] * inv - mu * mu;
        stats[bh * 2 + 0] = mu;
        stats[bh * 2 + 1] = rsqrtf(var + EPS_);
    }
}

// ---------------------------------------------------------------------------
// GroupNorm apply + transpose: y (B,H,TQ,HD) -> ybt (B,TQ,D)
// ---------------------------------------------------------------------------
__global__ void gn_apply_kernel(const float* __restrict__ y, const float* __restrict__ stats,
                                const float* __restrict__ gw, const float* __restrict__ gb,
                                float* __restrict__ ybt)
{
    const int i4 = blockIdx.x * blockDim.x + threadIdx.x;  // over B*TQ*D/4
    const int d4 = i4 & 255;           // D/4 positions
    const int t  = (i4 >> 8) & 1023;
    const int b  = i4 >> 18;
    const int c  = d4 * 4;
    const int h  = c >> 6;
    const int dd = c & 63;
    const float mu   = stats[(b * 16 + h) * 2 + 0];
    const float rstd = stats[(b * 16 + h) * 2 + 1];
    float4 v = *(const float4*)&y[(((size_t)(b * 16 + h)) * 1024 + t) * 64 + dd];
    float4 w = *(const float4*)&gw[c];
    float4 bb = *(const float4*)&gb[c];
    float4 o;
    o.x = (v.x - mu) * rstd * w.x + bb.x;
    o.y = (v.y - mu) * rstd * w.y + bb.y;
    o.z = (v.z - mu) * rstd * w.z + bb.z;
    o.w = (v.w - mu) * rstd * w.w + bb.w;
    *(float4*)&ybt[(size_t)i4 * 4] = o;
}

// ---------------------------------------------------------------------------
// Launch
// ---------------------------------------------------------------------------
extern "C" void kernel_launch(void* const* d_in, const int* in_sizes, int n_in,
                              void* d_out, int out_size)
{
    const float* x_q  = (const float*)d_in[0];
    const float* x_kv = (const float*)d_in[1];
    const float* Wq   = (const float*)d_in[2];
    const float* Wkv  = (const float*)d_in[3];
    const float* Wc   = (const float*)d_in[4];
    const float* qn1  = (const float*)d_in[5];
    const float* kn1  = (const float*)d_in[6];
    const float* qn2  = (const float*)d_in[7];
    const float* kn2  = (const float*)d_in[8];
    const float* gn_w = (const float*)d_in[9];
    const float* gn_b = (const float*)d_in[10];
    const float* lmb  = (const float*)d_in[11];
    float* out = (float*)d_out;

    float *qproj, *kvproj, *q1n, *q2n, *k1n, *k2n, *vh, *y, *ybt, *stats;
    cudaGetSymbolAddress((void**)&qproj,  g_qproj);
    cudaGetSymbolAddress((void**)&kvproj, g_kvproj);
    cudaGetSymbolAddress((void**)&q1n,    g_q1n);
    cudaGetSymbolAddress((void**)&q2n,    g_q2n);
    cudaGetSymbolAddress((void**)&k1n,    g_k1n);
    cudaGetSymbolAddress((void**)&k2n,    g_k2n);
    cudaGetSymbolAddress((void**)&vh,     g_vh);
    cudaGetSymbolAddress((void**)&y,      g_y);
    cudaGetSymbolAddress((void**)&ybt,    g_ybt);
    cudaGetSymbolAddress((void**)&stats,  g_stats);

    const int M = B_ * TQ_;  // 4096

    // 1) projections
    sgemm128<<<dim3(2 * D_ / 128, M / 128), 256>>>(x_q,  Wq,  qproj,  M, 2 * D_, D_);
    sgemm128<<<dim3(3 * D_ / 128, M / 128), 256>>>(x_kv, Wkv, kvproj, M, 3 * D_, D_);

    // 2) RMSNorm + head reshape
    {
        const int warps_q = M * H_ * 2;                 // 131072
        rms_q_kernel<<<warps_q * 32 / 256, 256>>>(qproj, qn1, qn2, q1n, q2n);
        const int warps_kv = M * H_ * 3;                // 196608
        rms_kv_kernel<<<warps_kv * 32 / 256, 256>>>(kvproj, kn1, kn2, k1n, k2n, vh);
    }

    // 3) fused dual flash attention
    cudaFuncSetAttribute(flash_kernel, cudaFuncAttributeMaxDynamicSharedMemorySize, FLASH_SMEM);
    flash_kernel<<<dim3(TQ_ / 64, H_, B_), 256, FLASH_SMEM>>>(q1n, q2n, k1n, k2n, vh, lmb, y);

    // 4) GroupNorm
    gn_stats_kernel<<<B_ * H_, 256>>>(y, stats);
    gn_apply_kernel<<<(B_ * TQ_ * D_ / 4) / 256, 256>>>(y, stats, gn_w, gn_b, ybt);

    // 5) output projection
    sgemm128<<<dim3(D_ / 128, M / 128), 256>>>(ybt, Wc, out, M, D_, D_);
}

// round 4
// speedup vs baseline: 1.3844x; 1.3844x over previous
#include <cuda_runtime.h>
#include <cuda_bf16.h>
#include <math.h>
#include <stdint.h>

// Problem constants
#define B_    4
#define TQ_   1024
#define TKV_  1024
#define D_    1024
#define H_    16
#define HD_   64
#define EPS_  1e-5f

// ===========================================================================
// PTX helpers (baseline features only — NO sm_103a-gated instructions)
// ===========================================================================
__device__ __forceinline__ uint32_t smem_to_u32(const void* smem_ptr) {
    uint32_t addr;
    asm("{ .reg .u64 tmp; cvta.to.shared.u64 tmp, %1; cvt.u32.u64 %0, tmp; }"
        : "=r"(addr) : "l"(smem_ptr));
    return addr;
}

__device__ __forceinline__ void cp_async16(uint32_t dst, const void* src) {
    asm volatile("cp.async.cg.shared.global [%0], [%1], 16;" :: "r"(dst), "l"(src));
}
#define CP_COMMIT() asm volatile("cp.async.commit_group;" ::: "memory")
#define CP_WAIT(n)  asm volatile("cp.async.wait_group %0;" :: "n"(n) : "memory")

__device__ __forceinline__ void ldsm_x4(uint32_t& r0, uint32_t& r1, uint32_t& r2,
                                        uint32_t& r3, uint32_t addr) {
    asm volatile("ldmatrix.sync.aligned.m8n8.x4.shared.b16 {%0,%1,%2,%3}, [%4];"
        : "=r"(r0), "=r"(r1), "=r"(r2), "=r"(r3) : "r"(addr));
}

// D += A * B  (m16n8k16, bf16 inputs, fp32 accum)
__device__ __forceinline__ void mma16816(float* d,
                                         uint32_t a0, uint32_t a1, uint32_t a2, uint32_t a3,
                                         uint32_t b0, uint32_t b1) {
    asm volatile(
        "mma.sync.aligned.m16n8k16.row.col.f32.bf16.bf16.f32 "
        "{%0,%1,%2,%3}, {%4,%5,%6,%7}, {%8,%9}, {%0,%1,%2,%3};"
        : "+f"(d[0]), "+f"(d[1]), "+f"(d[2]), "+f"(d[3])
        : "r"(a0), "r"(a1), "r"(a2), "r"(a3), "r"(b0), "r"(b1));
}

// ===========================================================================
// Device scratch
// ===========================================================================
__device__ float g_qproj [B_ * TQ_  * 2 * D_];
__device__ float g_kvproj[B_ * TKV_ * 3 * D_];
__device__ float g_q1n   [B_ * H_ * TQ_  * HD_];
__device__ float g_q2n   [B_ * H_ * TQ_  * HD_];
__device__ float g_k1n   [B_ * H_ * TKV_ * HD_];
__device__ float g_k2n   [B_ * H_ * TKV_ * HD_];
__device__ float g_vh    [B_ * H_ * TKV_ * HD_];
__device__ float g_y     [B_ * H_ * TQ_  * HD_];
__device__ float g_stats [B_ * H_ * 2];

__device__ __nv_bfloat16 g_xq_hi [B_ * TQ_ * D_];
__device__ __nv_bfloat16 g_xq_lo [B_ * TQ_ * D_];
__device__ __nv_bfloat16 g_xkv_hi[B_ * TKV_ * D_];
__device__ __nv_bfloat16 g_xkv_lo[B_ * TKV_ * D_];
__device__ __nv_bfloat16 g_wqt_hi [2 * D_ * D_];   // [2D, D] K-major
__device__ __nv_bfloat16 g_wqt_lo [2 * D_ * D_];
__device__ __nv_bfloat16 g_wkvt_hi[3 * D_ * D_];
__device__ __nv_bfloat16 g_wkvt_lo[3 * D_ * D_];
__device__ __nv_bfloat16 g_wct_hi [D_ * D_];
__device__ __nv_bfloat16 g_wct_lo [D_ * D_];
__device__ __nv_bfloat16 g_ybt_hi [B_ * TQ_ * D_];
__device__ __nv_bfloat16 g_ybt_lo [B_ * TQ_ * D_];

// ===========================================================================
// Split fp32 -> bf16 hi/lo
// ===========================================================================
__global__ void split_kernel(const float* __restrict__ x,
                             __nv_bfloat16* __restrict__ hi,
                             __nv_bfloat16* __restrict__ lo, int n4)
{
    const int i = blockIdx.x * blockDim.x + threadIdx.x;
    if (i >= n4) return;
    float4 v = ((const float4*)x)[i];
    float f[4] = {v.x, v.y, v.z, v.w};
    __nv_bfloat16 h[4], l[4];
    #pragma unroll
    for (int j = 0; j < 4; j++) {
        h[j] = __float2bfloat16_rn(f[j]);
        l[j] = __float2bfloat16_rn(f[j] - __bfloat162float(h[j]));
    }
    ((__nv_bfloat162*)hi)[2*i + 0] = __nv_bfloat162(h[0], h[1]);
    ((__nv_bfloat162*)hi)[2*i + 1] = __nv_bfloat162(h[2], h[3]);
    ((__nv_bfloat162*)lo)[2*i + 0] = __nv_bfloat162(l[0], l[1]);
    ((__nv_bfloat162*)lo)[2*i + 1] = __nv_bfloat162(l[2], l[3]);
}

// ===========================================================================
// Transpose + split: W [K,N] fp32 -> Wt_hi/lo [N,K] bf16 (K-major)
// ===========================================================================
__global__ void split_transpose_kernel(const float* __restrict__ W,
                                       __nv_bfloat16* __restrict__ hi,
                                       __nv_bfloat16* __restrict__ lo, int K, int N)
{
    __shared__ float t[32][33];
    const int n0 = blockIdx.x * 32, k0 = blockIdx.y * 32;
    #pragma unroll
    for (int dy = 0; dy < 32; dy += 8)
        t[threadIdx.y + dy][threadIdx.x] =
            W[(size_t)(k0 + threadIdx.y + dy) * N + n0 + threadIdx.x];
    __syncthreads();
    #pragma unroll
    for (int dy = 0; dy < 32; dy += 8) {
        const int n = n0 + threadIdx.y + dy, k = k0 + threadIdx.x;
        const float v = t[threadIdx.x][threadIdx.y + dy];
        const __nv_bfloat16 h = __float2bfloat16_rn(v);
        hi[(size_t)n * K + k] = h;
        lo[(size_t)n * K + k] = __float2bfloat16_rn(v - __bfloat162float(h));
    }
}

// ===========================================================================
// mma.sync bf16x3 GEMM: C[M,N] = A[M,K] @ Bt[N,K]^T   fp32 accum
// CTA 128x128, 8 warps (warp tile 64x32), K-chunk 32, double-buffered cp.async.
// smem row stride 40 bf16 (80 B) -> conflict-free ldmatrix.
// ===========================================================================
#define SAST       40                       // bf16 elements per smem row
#define GM_TILE_B  (128 * SAST * 2)         // 10240 bytes per operand tile
#define GM_STAGE_B (4 * GM_TILE_B)          // Ahi, Alo, Bhi, Blo
#define GM_SMEM    (2 * GM_STAGE_B)         // 81920 bytes

__device__ __forceinline__ void gm_load_stage(
    uint32_t stage_base, const __nv_bfloat16* const* srcs, int k0, int K, int tid)
{
    #pragma unroll
    for (int t = 0; t < 4; t++) {
        const __nv_bfloat16* s = srcs[t] + k0;
        const uint32_t tb = stage_base + t * GM_TILE_B;
        #pragma unroll
        for (int i = 0; i < 2; i++) {
            const int idx = tid + i * 256;       // 512 chunks of 16B
            const int row = idx >> 2, c16 = idx & 3;
            cp_async16(tb + row * (SAST * 2) + c16 * 16,
                       s + (size_t)row * K + c16 * 8);
        }
    }
    CP_COMMIT();
}

__global__ __launch_bounds__(256) void gemm_mma(
    const __nv_bfloat16* __restrict__ Ahi, const __nv_bfloat16* __restrict__ Alo,
    const __nv_bfloat16* __restrict__ Bhi, const __nv_bfloat16* __restrict__ Blo,
    float* __restrict__ C, int M, int N, int K)
{
    extern __shared__ __align__(128) char smem[];
    const uint32_t sb = smem_to_u32(smem);
    const int tid = threadIdx.x;
    const int lane = tid & 31;
    const int wid = tid >> 5;
    const int wm = wid & 1;          // 2 warps along M (64 rows each)
    const int wn = wid >> 1;         // 4 warps along N (32 cols each)
    const int bx = blockIdx.x, by = blockIdx.y;

    const __nv_bfloat16* srcs[4] = {
        Ahi + (size_t)(by * 128) * K, Alo + (size_t)(by * 128) * K,
        Bhi + (size_t)(bx * 128) * K, Blo + (size_t)(bx * 128) * K };

    float acc[4][4][4];
    #pragma unroll
    for (int a = 0; a < 4; a++)
        #pragma unroll
        for (int b = 0; b < 4; b++)
            #pragma unroll
            for (int c = 0; c < 4; c++) acc[a][b][c] = 0.f;

    const int nch = K >> 5;          // K / 32
    gm_load_stage(sb, srcs, 0, K, tid);

    // per-thread ldmatrix row/col offsets
    const uint32_t lrow = (lane & 15);
    const uint32_t lcol16 = (lane >> 4) * 16;  // byte offset of 8-col half

    for (int c = 0; c < nch; c++) {
        if (c + 1 < nch) gm_load_stage(sb + ((c + 1) & 1) * GM_STAGE_B, srcs, (c + 1) << 5, K, tid);
        if (c + 1 < nch) { CP_WAIT(1); } else { CP_WAIT(0); }
        __syncthreads();

        const uint32_t st = sb + (c & 1) * GM_STAGE_B;
        #pragma unroll
        for (int ks = 0; ks < 2; ks++) {
            const uint32_t coff = lcol16 + ks * 32;   // ks*16 bf16 = 32 B
            // B fragments (hi & lo) for 2 n16 tiles
            uint32_t bh[2][4], bl[2][4];
            #pragma unroll
            for (int nt = 0; nt < 2; nt++) {
                const uint32_t baddr = st + 2 * GM_TILE_B
                    + (wn * 32 + nt * 16 + lrow) * (SAST * 2) + coff;
                ldsm_x4(bh[nt][0], bh[nt][1], bh[nt][2], bh[nt][3], baddr);
                ldsm_x4(bl[nt][0], bl[nt][1], bl[nt][2], bl[nt][3], baddr + GM_TILE_B);
            }
            #pragma unroll
            for (int mt = 0; mt < 4; mt++) {
                const uint32_t aaddr = st
                    + (wm * 64 + mt * 16 + lrow) * (SAST * 2) + coff;
                uint32_t ah[4], al[4];
                ldsm_x4(ah[0], ah[1], ah[2], ah[3], aaddr);
                ldsm_x4(al[0], al[1], al[2], al[3], aaddr + GM_TILE_B);
                #pragma unroll
                for (int nt = 0; nt < 2; nt++) {
                    #pragma unroll
                    for (int hh = 0; hh < 2; hh++) {
                        float* d = acc[mt][nt * 2 + hh];
                        // frag {r_hh, r_hh+2}: n rows hh*8..hh*8+7
                        mma16816(d, ah[0], ah[1], ah[2], ah[3], bh[nt][hh], bh[nt][hh + 2]);
                        mma16816(d, ah[0], ah[1], ah[2], ah[3], bl[nt][hh], bl[nt][hh + 2]);
                        mma16816(d, al[0], al[1], al[2], al[3], bh[nt][hh], bh[nt][hh + 2]);
                    }
                }
            }
        }
        __syncthreads();
    }

    // epilogue: acc[mt][n8] regs {c0,c1}=(row, col..col+1), {c2,c3}=(row+8, ..)
    #pragma unroll
    for (int mt = 0; mt < 4; mt++) {
        const int row0 = by * 128 + wm * 64 + mt * 16 + (lane >> 2);
        #pragma unroll
        for (int n8 = 0; n8 < 4; n8++) {
            const int col = bx * 128 + wn * 32 + n8 * 8 + (lane & 3) * 2;
            float2 o0 = make_float2(acc[mt][n8][0], acc[mt][n8][1]);
            float2 o1 = make_float2(acc[mt][n8][2], acc[mt][n8][3]);
            *(float2*)&C[(size_t)row0 * N + col]       = o0;
            *(float2*)&C[(size_t)(row0 + 8) * N + col] = o1;
        }
    }
}

// ===========================================================================
// RMSNorm + head split for Q
// ===========================================================================
__global__ void rms_q_kernel(const float* __restrict__ qp,
                             const float* __restrict__ qn1, const float* __restrict__ qn2,
                             float* __restrict__ q1n, float* __restrict__ q2n)
{
    const int gw   = (blockIdx.x * blockDim.x + threadIdx.x) >> 5;
    const int lane = threadIdx.x & 31;
    const int which = gw & 1;
    const int h     = (gw >> 1) & 15;
    const int row   = gw >> 5;
    const float* src = qp + (size_t)row * 2048 + which * 1024 + h * 64 + lane * 2;
    float2 v = *(const float2*)src;
    float ss = v.x * v.x + v.y * v.y;
    #pragma unroll
    for (int o = 16; o; o >>= 1) ss += __shfl_xor_sync(0xffffffffu, ss, o);
    const float r = rsqrtf(ss * (1.0f / 64.0f) + EPS_);
    const int b = row >> 10, t = row & 1023;
    const float* w = (which ? qn2 : qn1) + lane * 2;
    float* dst = (which ? q2n : q1n)
               + (((size_t)b * 16 + h) * 1024 + t) * 64 + lane * 2;
    float2 o2;
    o2.x = v.x * r * w[0];
    o2.y = v.y * r * w[1];
    *(float2*)dst = o2;
}

// ===========================================================================
// RMSNorm + head split for KV
// ===========================================================================
__global__ void rms_kv_kernel(const float* __restrict__ kvp,
                              const float* __restrict__ kn1, const float* __restrict__ kn2,
                              float* __restrict__ k1n, float* __restrict__ k2n,
                              float* __restrict__ vh)
{
    const int gw   = (blockIdx.x * blockDim.x + threadIdx.x) >> 5;
    const int lane = threadIdx.x & 31;
    const int which = gw % 3;
    const int rh    = gw / 3;
    const int h     = rh & 15;
    const int row   = rh >> 4;
    const float* src = kvp + (size_t)row * 3072 + which * 1024 + h * 64 + lane * 2;
    float2 v = *(const float2*)src;
    float r = 1.0f;
    float w0 = 1.0f, w1 = 1.0f;
    if (which < 2) {
        float ss = v.x * v.x + v.y * v.y;
        #pragma unroll
        for (int o = 16; o; o >>= 1) ss += __shfl_xor_sync(0xffffffffu, ss, o);
        r = rsqrtf(ss * (1.0f / 64.0f) + EPS_);
        const float* w = (which ? kn2 : kn1) + lane * 2;
        w0 = w[0]; w1 = w[1];
    }
    const int b = row >> 10, t = row & 1023;
    float* dst = (which == 0 ? k1n : (which == 1 ? k2n : vh))
               + (((size_t)b * 16 + h) * 1024 + t) * 64 + lane * 2;
    float2 o2;
    o2.x = v.x * r * w0;
    o2.y = v.y * r * w1;
    *(float2*)dst = o2;
}

// ===========================================================================
// Fused dual flash attention (fp32 SIMT — unchanged from passing round)
// ===========================================================================
#define SSTR 68

__device__ __forceinline__ void compute_S(const float* sQ, const float* sK,
                                          float* sS, int tr, int tc)
{
    float s[4][4];
    #pragma unroll
    for (int i = 0; i < 4; i++)
        #pragma unroll
        for (int j = 0; j < 4; j++) s[i][j] = 0.f;

    #pragma unroll
    for (int d4 = 0; d4 < 16; d4++) {
        float4 q[4], k[4];
        #pragma unroll
        for (int i = 0; i < 4; i++)
            q[i] = *(const float4*)&sQ[(tr + 16 * i) * SSTR + d4 * 4];
        #pragma unroll
        for (int j = 0; j < 4; j++)
            k[j] = *(const float4*)&sK[(tc + 16 * j) * SSTR + d4 * 4];
        #pragma unroll
        for (int i = 0; i < 4; i++)
            #pragma unroll
            for (int j = 0; j < 4; j++)
                s[i][j] += q[i].x * k[j].x + q[i].y * k[j].y
                         + q[i].z * k[j].z + q[i].w * k[j].w;
    }
    #pragma unroll
    for (int i = 0; i < 4; i++)
        #pragma unroll
        for (int j = 0; j < 4; j++)
            sS[(tr + 16 * i) * SSTR + tc + 16 * j] = s[i][j];
}

__device__ __forceinline__ void softmax_update(float* sS, float* smv, float* slv,
                                               float* sal, int tid)
{
    const int row = tid >> 2, part = tid & 3;
    float* p = &sS[row * SSTR + part * 16];
    float mx = -1e30f;
    #pragma unroll
    for (int i = 0; i < 16; i++) mx = fmaxf(mx, p[i]);
    mx = fmaxf(mx, __shfl_xor_sync(0xffffffffu, mx, 1));
    mx = fmaxf(mx, __shfl_xor_sync(0xffffffffu, mx, 2));
    const float mold = smv[row];
    const float mnew = fmaxf(mold, mx);
    const float alpha = __expf(mold - mnew);
    float ps = 0.f;
    #pragma unroll
    for (int i = 0; i < 16; i++) {
        float e = __expf(p[i] - mnew);
        p[i] = e;
        ps += e;
    }
    ps += __shfl_xor_sync(0xffffffffu, ps, 1);
    ps += __shfl_xor_sync(0xffffffffu, ps, 2);
    if (part == 0) {
        smv[row] = mnew;
        slv[row] = slv[row] * alpha + ps;
        sal[row] = alpha;
    }
}

__device__ __forceinline__ void pv_accum(float acc[4][4], const float* sS,
                                         const float* sV, const float* sal,
                                         int tr, int tc)
{
    #pragma unroll
    for (int i = 0; i < 4; i++) {
        const float a = sal[tr + 16 * i];
        #pragma unroll
        for (int k = 0; k < 4; k++) acc[i][k] *= a;
    }
    #pragma unroll
    for (int j4 = 0; j4 < 16; j4++) {
        float4 pr[4];
        #pragma unroll
        for (int i = 0; i < 4; i++)
            pr[i] = *(const float4*)&sS[(tr + 16 * i) * SSTR + j4 * 4];
        float4 v4[4];
        #pragma unroll
        for (int jj = 0; jj < 4; jj++)
            v4[jj] = *(const float4*)&sV[(j4 * 4 + jj) * SSTR + tc * 4];
        #pragma unroll
        for (int i = 0; i < 4; i++) {
            const float* pf = (const float*)&pr[i];
            #pragma unroll
            for (int jj = 0; jj < 4; jj++) {
                acc[i][0] += pf[jj] * v4[jj].x;
                acc[i][1] += pf[jj] * v4[jj].y;
                acc[i][2] += pf[jj] * v4[jj].z;
                acc[i][3] += pf[jj] * v4[jj].w;
            }
        }
    }
}

#define FLASH_SMEM ((6 * 64 * SSTR + 5 * 64) * (int)sizeof(float))

__global__ __launch_bounds__(256) void flash_kernel(
    const float* __restrict__ q1n, const float* __restrict__ q2n,
    const float* __restrict__ k1n, const float* __restrict__ k2n,
    const float* __restrict__ vh,  const float* __restrict__ lmb,
    float* __restrict__ y)
{
    extern __shared__ float smbuf[];
    float* sQ1 = smbuf;
    float* sQ2 = sQ1 + 64 * SSTR;
    float* sK1 = sQ2 + 64 * SSTR;
    float* sK2 = sK1 + 64 * SSTR;
    float* sV  = sK2 + 64 * SSTR;
    float* sS  = sV  + 64 * SSTR;
    float* sm1 = sS  + 64 * SSTR;
    float* sl1 = sm1 + 64;
    float* sm2 = sl1 + 64;
    float* sl2 = sm2 + 64;
    float* sal = sl2 + 64;

    const int tid = threadIdx.x;
    const int qt = blockIdx.x, h = blockIdx.y, b = blockIdx.z;
    const int bh = b * H_ + h;
    const size_t qbase  = ((size_t)bh * TQ_ + qt * 64) * HD_;
    const size_t kvbase = (size_t)bh * TKV_ * HD_;

    for (int i = tid; i < 64 * 16; i += 256) {
        const int r = i >> 4, c4 = (i & 15) << 2;
        float4 a = *(const float4*)&q1n[qbase + (size_t)r * HD_ + c4];
        a.x *= 0.125f; a.y *= 0.125f; a.z *= 0.125f; a.w *= 0.125f;
        *(float4*)&sQ1[r * SSTR + c4] = a;
        float4 bq = *(const float4*)&q2n[qbase + (size_t)r * HD_ + c4];
        bq.x *= 0.125f; bq.y *= 0.125f; bq.z *= 0.125f; bq.w *= 0.125f;
        *(float4*)&sQ2[r * SSTR + c4] = bq;
    }
    if (tid < 64) {
        sm1[tid] = -1e30f; sl1[tid] = 0.f;
        sm2[tid] = -1e30f; sl2[tid] = 0.f;
    }

    float acc1[4][4], acc2[4][4];
    #pragma unroll
    for (int i = 0; i < 4; i++)
        #pragma unroll
        for (int k = 0; k < 4; k++) { acc1[i][k] = 0.f; acc2[i][k] = 0.f; }

    const int tr = tid & 15;
    const int tc = tid >> 4;

    for (int kt = 0; kt < TKV_ / 64; kt++) {
        __syncthreads();
        const size_t koff = kvbase + (size_t)kt * 64 * HD_;
        for (int i = tid; i < 64 * 16; i += 256) {
            const int r = i >> 4, c4 = (i & 15) << 2;
            *(float4*)&sK1[r * SSTR + c4] = *(const float4*)&k1n[koff + (size_t)r * HD_ + c4];
            *(float4*)&sK2[r * SSTR + c4] = *(const float4*)&k2n[koff + (size_t)r * HD_ + c4];
            *(float4*)&sV [r * SSTR + c4] = *(const float4*)&vh [koff + (size_t)r * HD_ + c4];
        }
        __syncthreads();
        compute_S(sQ1, sK1, sS, tr, tc);
        __syncthreads();
        softmax_update(sS, sm1, sl1, sal, tid);
        __syncthreads();
        pv_accum(acc1, sS, sV, sal, tr, tc);
        __syncthreads();
        compute_S(sQ2, sK2, sS, tr, tc);
        __syncthreads();
        softmax_update(sS, sm2, sl2, sal, tid);
        __syncthreads();
        pv_accum(acc2, sS, sV, sal, tr, tc);
    }
    __syncthreads();

    const float cmul = log1pf(__expf(lmb[h]));
    #pragma unroll
    for (int i = 0; i < 4; i++) {
        const int r = tr + 16 * i;
        const float il1 = 1.f / sl1[r];
        const float il2 = cmul / sl2[r];
        float4 o;
        o.x = acc1[i][0] * il1 - acc2[i][0] * il2;
        o.y = acc1[i][1] * il1 - acc2[i][1] * il2;
        o.z = acc1[i][2] * il1 - acc2[i][2] * il2;
        o.w = acc1[i][3] * il1 - acc2[i][3] * il2;
        *(float4*)&y[qbase + (size_t)r * HD_ + tc * 4] = o;
    }
}

// ===========================================================================
// GroupNorm stats
// ===========================================================================
__global__ void gn_stats_kernel(const float* __restrict__ y, float* __restrict__ stats)
{
    __shared__ float rs[256], rq[256];
    const int bh = blockIdx.x, tid = threadIdx.x;
    const float* p = y + (size_t)bh * TQ_ * HD_;
    float s = 0.f, q = 0.f;
    for (int i = tid * 4; i < TQ_ * HD_; i += 256 * 4) {
        float4 v = *(const float4*)(p + i);
        s += v.x + v.y + v.z + v.w;
        q += v.x * v.x + v.y * v.y + v.z * v.z + v.w * v.w;
    }
    rs[tid] = s; rq[tid] = q;
    __syncthreads();
    for (int o = 128; o; o >>= 1) {
        if (tid < o) { rs[tid] += rs[tid + o]; rq[tid] += rq[tid + o]; }
        __syncthreads();
    }
    if (tid == 0) {
        const float inv = 1.f / (float)(TQ_ * HD_);
        const float mu = rs[0] * inv;
        const float var = rq[0] * inv - mu * mu;
        stats[bh * 2 + 0] = mu;
        stats[bh * 2 + 1] = rsqrtf(var + EPS_);
    }
}

// ===========================================================================
// GroupNorm apply + transpose + bf16 hi/lo split
// ===========================================================================
__global__ void gn_apply_kernel(const float* __restrict__ y, const float* __restrict__ stats,
                                const float* __restrict__ gw, const float* __restrict__ gb,
                                __nv_bfloat16* __restrict__ hi, __nv_bfloat16* __restrict__ lo)
{
    const int i4 = blockIdx.x * blockDim.x + threadIdx.x;
    const int d4 = i4 & 255;
    const int t  = (i4 >> 8) & 1023;
    const int b  = i4 >> 18;
    const int c  = d4 * 4;
    const int h  = c >> 6;
    const int dd = c & 63;
    const float mu   = stats[(b * 16 + h) * 2 + 0];
    const float rstd = stats[(b * 16 + h) * 2 + 1];
    float4 v = *(const float4*)&y[(((size_t)(b * 16 + h)) * 1024 + t) * 64 + dd];
    float4 w = *(const float4*)&gw[c];
    float4 bb = *(const float4*)&gb[c];
    float f[4];
    f[0] = (v.x - mu) * rstd * w.x + bb.x;
    f[1] = (v.y - mu) * rstd * w.y + bb.y;
    f[2] = (v.z - mu) * rstd * w.z + bb.z;
    f[3] = (v.w - mu) * rstd * w.w + bb.w;
    __nv_bfloat16 hb[4], lb[4];
    #pragma unroll
    for (int j = 0; j < 4; j++) {
        hb[j] = __float2bfloat16_rn(f[j]);
        lb[j] = __float2bfloat16_rn(f[j] - __bfloat162float(hb[j]));
    }
    ((__nv_bfloat162*)hi)[2*i4 + 0] = __nv_bfloat162(hb[0], hb[1]);
    ((__nv_bfloat162*)hi)[2*i4 + 1] = __nv_bfloat162(hb[2], hb[3]);
    ((__nv_bfloat162*)lo)[2*i4 + 0] = __nv_bfloat162(lb[0], lb[1]);
    ((__nv_bfloat162*)lo)[2*i4 + 1] = __nv_bfloat162(lb[2], lb[3]);
}

// ===========================================================================
// Launch
// ===========================================================================
extern "C" void kernel_launch(void* const* d_in, const int* in_sizes, int n_in,
                              void* d_out, int out_size)
{
    const float* x_q  = (const float*)d_in[0];
    const float* x_kv = (const float*)d_in[1];
    const float* Wq   = (const float*)d_in[2];
    const float* Wkv  = (const float*)d_in[3];
    const float* Wc   = (const float*)d_in[4];
    const float* qn1  = (const float*)d_in[5];
    const float* kn1  = (const float*)d_in[6];
    const float* qn2  = (const float*)d_in[7];
    const float* kn2  = (const float*)d_in[8];
    const float* gn_w = (const float*)d_in[9];
    const float* gn_b = (const float*)d_in[10];
    const float* lmb  = (const float*)d_in[11];
    float* out = (float*)d_out;

    float *qproj, *kvproj, *q1n, *q2n, *k1n, *k2n, *vh, *y, *stats;
    cudaGetSymbolAddress((void**)&qproj,  g_qproj);
    cudaGetSymbolAddress((void**)&kvproj, g_kvproj);
    cudaGetSymbolAddress((void**)&q1n,    g_q1n);
    cudaGetSymbolAddress((void**)&q2n,    g_q2n);
    cudaGetSymbolAddress((void**)&k1n,    g_k1n);
    cudaGetSymbolAddress((void**)&k2n,    g_k2n);
    cudaGetSymbolAddress((void**)&vh,     g_vh);
    cudaGetSymbolAddress((void**)&y,      g_y);
    cudaGetSymbolAddress((void**)&stats,  g_stats);

    __nv_bfloat16 *xq_hi, *xq_lo, *xkv_hi, *xkv_lo;
    __nv_bfloat16 *wqt_hi, *wqt_lo, *wkvt_hi, *wkvt_lo, *wct_hi, *wct_lo;
    __nv_bfloat16 *ybt_hi, *ybt_lo;
    cudaGetSymbolAddress((void**)&xq_hi,   g_xq_hi);
    cudaGetSymbolAddress((void**)&xq_lo,   g_xq_lo);
    cudaGetSymbolAddress((void**)&xkv_hi,  g_xkv_hi);
    cudaGetSymbolAddress((void**)&xkv_lo,  g_xkv_lo);
    cudaGetSymbolAddress((void**)&wqt_hi,  g_wqt_hi);
    cudaGetSymbolAddress((void**)&wqt_lo,  g_wqt_lo);
    cudaGetSymbolAddress((void**)&wkvt_hi, g_wkvt_hi);
    cudaGetSymbolAddress((void**)&wkvt_lo, g_wkvt_lo);
    cudaGetSymbolAddress((void**)&wct_hi,  g_wct_hi);
    cudaGetSymbolAddress((void**)&wct_lo,  g_wct_lo);
    cudaGetSymbolAddress((void**)&ybt_hi,  g_ybt_hi);
    cudaGetSymbolAddress((void**)&ybt_lo,  g_ybt_lo);

    const int M = B_ * TQ_;  // 4096

    cudaFuncSetAttribute(gemm_mma, cudaFuncAttributeMaxDynamicSharedMemorySize, GM_SMEM);
    cudaFuncSetAttribute(flash_kernel, cudaFuncAttributeMaxDynamicSharedMemorySize, FLASH_SMEM);

    // 0) split/convert operands to bf16 hi/lo
    {
        const int n4 = M * D_ / 4;
        split_kernel<<<n4 / 256, 256>>>(x_q,  xq_hi,  xq_lo,  n4);
        split_kernel<<<n4 / 256, 256>>>(x_kv, xkv_hi, xkv_lo, n4);
        split_transpose_kernel<<<dim3(2 * D_ / 32, D_ / 32), dim3(32, 8)>>>(Wq,  wqt_hi,  wqt_lo,  D_, 2 * D_);
        split_transpose_kernel<<<dim3(3 * D_ / 32, D_ / 32), dim3(32, 8)>>>(Wkv, wkvt_hi, wkvt_lo, D_, 3 * D_);
        split_transpose_kernel<<<dim3(D_ / 32, D_ / 32),     dim3(32, 8)>>>(Wc,  wct_hi,  wct_lo,  D_, D_);
    }

    // 1) projections (mma.sync bf16x3)
    gemm_mma<<<dim3(2 * D_ / 128, M / 128), 256, GM_SMEM>>>(xq_hi,  xq_lo,  wqt_hi,  wqt_lo,  qproj,  M, 2 * D_, D_);
    gemm_mma<<<dim3(3 * D_ / 128, M / 128), 256, GM_SMEM>>>(xkv_hi, xkv_lo, wkvt_hi, wkvt_lo, kvproj, M, 3 * D_, D_);

    // 2) RMSNorm + head reshape
    rms_q_kernel<<<M * H_ * 2 * 32 / 256, 256>>>(qproj, qn1, qn2, q1n, q2n);
    rms_kv_kernel<<<M * H_ * 3 * 32 / 256, 256>>>(kvproj, kn1, kn2, k1n, k2n, vh);

    // 3) fused dual flash attention
    flash_kernel<<<dim3(TQ_ / 64, H_, B_), 256, FLASH_SMEM>>>(q1n, q2n, k1n, k2n, vh, lmb, y);

    // 4) GroupNorm
    gn_stats_kernel<<<B_ * H_, 256>>>(y, stats);
    gn_apply_kernel<<<(B_ * TQ_ * D_ / 4) / 256, 256>>>(y, stats, gn_w, gn_b, ybt_hi, ybt_lo);

    // 5) output projection (mma.sync bf16x3)
    gemm_mma<<<dim3(D_ / 128, M / 128), 256, GM_SMEM>>>(ybt_hi, ybt_lo, wct_hi, wct_lo, out, M, D_, D_);
}

// round 6
// speedup vs baseline: 2.2675x; 1.6378x over previous
#include <cuda_runtime.h>
#include <cuda_bf16.h>
#include <math.h>
#include <stdint.h>

// Problem constants
#define B_    4
#define TQ_   1024
#define TKV_  1024
#define D_    1024
#define H_    16
#define HD_   64
#define EPS_  1e-5f

// ===========================================================================
// PTX helpers (baseline features only — compute_103 virtual arch safe)
// ===========================================================================
__device__ __forceinline__ uint32_t smem_to_u32(const void* smem_ptr) {
    uint32_t addr;
    asm("{ .reg .u64 tmp; cvta.to.shared.u64 tmp, %1; cvt.u32.u64 %0, tmp; }"
        : "=r"(addr) : "l"(smem_ptr));
    return addr;
}

__device__ __forceinline__ void cp_async16(uint32_t dst, const void* src) {
    asm volatile("cp.async.cg.shared.global [%0], [%1], 16;" :: "r"(dst), "l"(src));
}
#define CP_COMMIT() asm volatile("cp.async.commit_group;" ::: "memory")
#define CP_WAIT(n)  asm volatile("cp.async.wait_group %0;" :: "n"(n) : "memory")

__device__ __forceinline__ void ldsm_x4(uint32_t& r0, uint32_t& r1, uint32_t& r2,
                                        uint32_t& r3, uint32_t addr) {
    asm volatile("ldmatrix.sync.aligned.m8n8.x4.shared.b16 {%0,%1,%2,%3}, [%4];"
        : "=r"(r0), "=r"(r1), "=r"(r2), "=r"(r3) : "r"(addr));
}

__device__ __forceinline__ void ldsm_x4_t(uint32_t& r0, uint32_t& r1, uint32_t& r2,
                                          uint32_t& r3, uint32_t addr) {
    asm volatile("ldmatrix.sync.aligned.m8n8.x4.trans.shared.b16 {%0,%1,%2,%3}, [%4];"
        : "=r"(r0), "=r"(r1), "=r"(r2), "=r"(r3) : "r"(addr));
}

// D += A * B  (m16n8k16, bf16 inputs, fp32 accum)
__device__ __forceinline__ void mma16816(float* d, const uint32_t* a,
                                         uint32_t b0, uint32_t b1) {
    asm volatile(
        "mma.sync.aligned.m16n8k16.row.col.f32.bf16.bf16.f32 "
        "{%0,%1,%2,%3}, {%4,%5,%6,%7}, {%8,%9}, {%0,%1,%2,%3};"
        : "+f"(d[0]), "+f"(d[1]), "+f"(d[2]), "+f"(d[3])
        : "r"(a[0]), "r"(a[1]), "r"(a[2]), "r"(a[3]), "r"(b0), "r"(b1));
}

__device__ __forceinline__ uint32_t pack_bf16(float a, float b) {
    __nv_bfloat162 t = __floats2bfloat162_rn(a, b);
    return *reinterpret_cast<uint32_t*>(&t);
}

// ===========================================================================
// Device scratch
// ===========================================================================
__device__ float g_qproj [B_ * TQ_  * 2 * D_];
__device__ float g_kvproj[B_ * TKV_ * 3 * D_];
__device__ float g_y     [B_ * H_ * TQ_  * HD_];
__device__ float g_stats [B_ * H_ * 2];

__device__ __nv_bfloat16 g_xq_hi [B_ * TQ_ * D_];
__device__ __nv_bfloat16 g_xq_lo [B_ * TQ_ * D_];
__device__ __nv_bfloat16 g_xkv_hi[B_ * TKV_ * D_];
__device__ __nv_bfloat16 g_xkv_lo[B_ * TKV_ * D_];
__device__ __nv_bfloat16 g_wqt_hi [2 * D_ * D_];
__device__ __nv_bfloat16 g_wqt_lo [2 * D_ * D_];
__device__ __nv_bfloat16 g_wkvt_hi[3 * D_ * D_];
__device__ __nv_bfloat16 g_wkvt_lo[3 * D_ * D_];
__device__ __nv_bfloat16 g_wct_hi [D_ * D_];
__device__ __nv_bfloat16 g_wct_lo [D_ * D_];
__device__ __nv_bfloat16 g_ybt_hi [B_ * TQ_ * D_];
__device__ __nv_bfloat16 g_ybt_lo [B_ * TQ_ * D_];

// bf16 hi/lo attention operands, (B,H,T,HD)
__device__ __nv_bfloat16 g_q1h[B_ * H_ * TQ_ * HD_];
__device__ __nv_bfloat16 g_q1l[B_ * H_ * TQ_ * HD_];
__device__ __nv_bfloat16 g_q2h[B_ * H_ * TQ_ * HD_];
__device__ __nv_bfloat16 g_q2l[B_ * H_ * TQ_ * HD_];
__device__ __nv_bfloat16 g_k1h[B_ * H_ * TKV_ * HD_];
__device__ __nv_bfloat16 g_k1l[B_ * H_ * TKV_ * HD_];
__device__ __nv_bfloat16 g_k2h[B_ * H_ * TKV_ * HD_];
__device__ __nv_bfloat16 g_k2l[B_ * H_ * TKV_ * HD_];
__device__ __nv_bfloat16 g_vhh[B_ * H_ * TKV_ * HD_];
__device__ __nv_bfloat16 g_vhl[B_ * H_ * TKV_ * HD_];

// ===========================================================================
// Split fp32 -> bf16 hi/lo
// ===========================================================================
__global__ void split_kernel(const float* __restrict__ x,
                             __nv_bfloat16* __restrict__ hi,
                             __nv_bfloat16* __restrict__ lo, int n4)
{
    const int i = blockIdx.x * blockDim.x + threadIdx.x;
    if (i >= n4) return;
    float4 v = ((const float4*)x)[i];
    float f[4] = {v.x, v.y, v.z, v.w};
    __nv_bfloat16 h[4], l[4];
    #pragma unroll
    for (int j = 0; j < 4; j++) {
        h[j] = __float2bfloat16_rn(f[j]);
        l[j] = __float2bfloat16_rn(f[j] - __bfloat162float(h[j]));
    }
    ((__nv_bfloat162*)hi)[2*i + 0] = __nv_bfloat162(h[0], h[1]);
    ((__nv_bfloat162*)hi)[2*i + 1] = __nv_bfloat162(h[2], h[3]);
    ((__nv_bfloat162*)lo)[2*i + 0] = __nv_bfloat162(l[0], l[1]);
    ((__nv_bfloat162*)lo)[2*i + 1] = __nv_bfloat162(l[2], l[3]);
}

// ===========================================================================
// Transpose + split: W [K,N] fp32 -> Wt_hi/lo [N,K] bf16 (K-major)
// ===========================================================================
__global__ void split_transpose_kernel(const float* __restrict__ W,
                                       __nv_bfloat16* __restrict__ hi,
                                       __nv_bfloat16* __restrict__ lo, int K, int N)
{
    __shared__ float t[32][33];
    const int n0 = blockIdx.x * 32, k0 = blockIdx.y * 32;
    #pragma unroll
    for (int dy = 0; dy < 32; dy += 8)
        t[threadIdx.y + dy][threadIdx.x] =
            W[(size_t)(k0 + threadIdx.y + dy) * N + n0 + threadIdx.x];
    __syncthreads();
    #pragma unroll
    for (int dy = 0; dy < 32; dy += 8) {
        const int n = n0 + threadIdx.y + dy, k = k0 + threadIdx.x;
        const float v = t[threadIdx.x][threadIdx.y + dy];
        const __nv_bfloat16 h = __float2bfloat16_rn(v);
        hi[(size_t)n * K + k] = h;
        lo[(size_t)n * K + k] = __float2bfloat16_rn(v - __bfloat162float(h));
    }
}

// ===========================================================================
// mma.sync bf16x3 GEMM (unchanged from passing round)
// ===========================================================================
#define SAST       40
#define GM_TILE_B  (128 * SAST * 2)
#define GM_STAGE_B (4 * GM_TILE_B)
#define GM_SMEM    (2 * GM_STAGE_B)

__device__ __forceinline__ void gm_load_stage(
    uint32_t stage_base, const __nv_bfloat16* const* srcs, int k0, int K, int tid)
{
    #pragma unroll
    for (int t = 0; t < 4; t++) {
        const __nv_bfloat16* s = srcs[t] + k0;
        const uint32_t tb = stage_base + t * GM_TILE_B;
        #pragma unroll
        for (int i = 0; i < 2; i++) {
            const int idx = tid + i * 256;
            const int row = idx >> 2, c16 = idx & 3;
            cp_async16(tb + row * (SAST * 2) + c16 * 16,
                       s + (size_t)row * K + c16 * 8);
        }
    }
    CP_COMMIT();
}

__global__ __launch_bounds__(256) void gemm_mma(
    const __nv_bfloat16* __restrict__ Ahi, const __nv_bfloat16* __restrict__ Alo,
    const __nv_bfloat16* __restrict__ Bhi, const __nv_bfloat16* __restrict__ Blo,
    float* __restrict__ C, int M, int N, int K)
{
    extern __shared__ __align__(128) char smem[];
    const uint32_t sb = smem_to_u32(smem);
    const int tid = threadIdx.x;
    const int lane = tid & 31;
    const int wid = tid >> 5;
    const int wm = wid & 1;
    const int wn = wid >> 1;
    const int bx = blockIdx.x, by = blockIdx.y;

    const __nv_bfloat16* srcs[4] = {
        Ahi + (size_t)(by * 128) * K, Alo + (size_t)(by * 128) * K,
        Bhi + (size_t)(bx * 128) * K, Blo + (size_t)(bx * 128) * K };

    float acc[4][4][4];
    #pragma unroll
    for (int a = 0; a < 4; a++)
        #pragma unroll
        for (int b = 0; b < 4; b++)
            #pragma unroll
            for (int c = 0; c < 4; c++) acc[a][b][c] = 0.f;

    const int nch = K >> 5;
    gm_load_stage(sb, srcs, 0, K, tid);

    const uint32_t lrow = (lane & 15);
    const uint32_t lcol16 = (lane >> 4) * 16;

    for (int c = 0; c < nch; c++) {
        if (c + 1 < nch) gm_load_stage(sb + ((c + 1) & 1) * GM_STAGE_B, srcs, (c + 1) << 5, K, tid);
        if (c + 1 < nch) { CP_WAIT(1); } else { CP_WAIT(0); }
        __syncthreads();

        const uint32_t st = sb + (c & 1) * GM_STAGE_B;
        #pragma unroll
        for (int ks = 0; ks < 2; ks++) {
            const uint32_t coff = lcol16 + ks * 32;
            uint32_t bh[2][4], bl[2][4];
            #pragma unroll
            for (int nt = 0; nt < 2; nt++) {
                const uint32_t baddr = st + 2 * GM_TILE_B
                    + (wn * 32 + nt * 16 + lrow) * (SAST * 2) + coff;
                ldsm_x4(bh[nt][0], bh[nt][1], bh[nt][2], bh[nt][3], baddr);
                ldsm_x4(bl[nt][0], bl[nt][1], bl[nt][2], bl[nt][3], baddr + GM_TILE_B);
            }
            #pragma unroll
            for (int mt = 0; mt < 4; mt++) {
                const uint32_t aaddr = st
                    + (wm * 64 + mt * 16 + lrow) * (SAST * 2) + coff;
                uint32_t ah[4], al[4];
                ldsm_x4(ah[0], ah[1], ah[2], ah[3], aaddr);
                ldsm_x4(al[0], al[1], al[2], al[3], aaddr + GM_TILE_B);
                #pragma unroll
                for (int nt = 0; nt < 2; nt++) {
                    #pragma unroll
                    for (int hh = 0; hh < 2; hh++) {
                        float* d = acc[mt][nt * 2 + hh];
                        uint32_t bfh0 = bh[nt][hh], bfh1 = bh[nt][hh + 2];
                        mma16816(d, ah, bfh0, bfh1);
                        mma16816(d, ah, bl[nt][hh], bl[nt][hh + 2]);
                        mma16816(d, al, bfh0, bfh1);
                    }
                }
            }
        }
        __syncthreads();
    }

    #pragma unroll
    for (int mt = 0; mt < 4; mt++) {
        const int row0 = by * 128 + wm * 64 + mt * 16 + (lane >> 2);
        #pragma unroll
        for (int n8 = 0; n8 < 4; n8++) {
            const int col = bx * 128 + wn * 32 + n8 * 8 + (lane & 3) * 2;
            float2 o0 = make_float2(acc[mt][n8][0], acc[mt][n8][1]);
            float2 o1 = make_float2(acc[mt][n8][2], acc[mt][n8][3]);
            *(float2*)&C[(size_t)row0 * N + col]       = o0;
            *(float2*)&C[(size_t)(row0 + 8) * N + col] = o1;
        }
    }
}

// ===========================================================================
// RMSNorm + head split for Q -> bf16 hi/lo, prescaled by 1/8
// ===========================================================================
__global__ void rms_q_kernel(const float* __restrict__ qp,
                             const float* __restrict__ qn1, const float* __restrict__ qn2,
                             __nv_bfloat16* __restrict__ q1h, __nv_bfloat16* __restrict__ q1l,
                             __nv_bfloat16* __restrict__ q2h, __nv_bfloat16* __restrict__ q2l)
{
    const int gw   = (blockIdx.x * blockDim.x + threadIdx.x) >> 5;
    const int lane = threadIdx.x & 31;
    const int which = gw & 1;
    const int h     = (gw >> 1) & 15;
    const int row   = gw >> 5;
    const float* src = qp + (size_t)row * 2048 + which * 1024 + h * 64 + lane * 2;
    float2 v = *(const float2*)src;
    float ss = v.x * v.x + v.y * v.y;
    #pragma unroll
    for (int o = 16; o; o >>= 1) ss += __shfl_xor_sync(0xffffffffu, ss, o);
    const float r = rsqrtf(ss * (1.0f / 64.0f) + EPS_);
    const int b = row >> 10, t = row & 1023;
    const float* w = (which ? qn2 : qn1) + lane * 2;
    const float f0 = v.x * r * w[0] * 0.125f;
    const float f1 = v.y * r * w[1] * 0.125f;
    const __nv_bfloat16 h0 = __float2bfloat16_rn(f0);
    const __nv_bfloat16 h1 = __float2bfloat16_rn(f1);
    const __nv_bfloat16 l0 = __float2bfloat16_rn(f0 - __bfloat162float(h0));
    const __nv_bfloat16 l1 = __float2bfloat16_rn(f1 - __bfloat162float(h1));
    const size_t e2 = ((((size_t)b * 16 + h) * 1024 + t) * 64 + lane * 2) >> 1;
    __nv_bfloat16* dh = which ? q2h : q1h;
    __nv_bfloat16* dl = which ? q2l : q1l;
    ((__nv_bfloat162*)dh)[e2] = __nv_bfloat162(h0, h1);
    ((__nv_bfloat162*)dl)[e2] = __nv_bfloat162(l0, l1);
}

// ===========================================================================
// RMSNorm + head split for KV -> bf16 hi/lo
// ===========================================================================
__global__ void rms_kv_kernel(const float* __restrict__ kvp,
                              const float* __restrict__ kn1, const float* __restrict__ kn2,
                              __nv_bfloat16* __restrict__ k1h, __nv_bfloat16* __restrict__ k1l,
                              __nv_bfloat16* __restrict__ k2h, __nv_bfloat16* __restrict__ k2l,
                              __nv_bfloat16* __restrict__ vhh, __nv_bfloat16* __restrict__ vhl)
{
    const int gw   = (blockIdx.x * blockDim.x + threadIdx.x) >> 5;
    const int lane = threadIdx.x & 31;
    const int which = gw % 3;
    const int rh    = gw / 3;
    const int h     = rh & 15;
    const int row   = rh >> 4;
    const float* src = kvp + (size_t)row * 3072 + which * 1024 + h * 64 + lane * 2;
    float2 v = *(const float2*)src;
    float r = 1.0f;
    float w0 = 1.0f, w1 = 1.0f;
    if (which < 2) {
        float ss = v.x * v.x + v.y * v.y;
        #pragma unroll
        for (int o = 16; o; o >>= 1) ss += __shfl_xor_sync(0xffffffffu, ss, o);
        r = rsqrtf(ss * (1.0f / 64.0f) + EPS_);
        const float* w = (which ? kn2 : kn1) + lane * 2;
        w0 = w[0]; w1 = w[1];
    }
    const float f0 = v.x * r * w0;
    const float f1 = v.y * r * w1;
    const __nv_bfloat16 h0 = __float2bfloat16_rn(f0);
    const __nv_bfloat16 h1 = __float2bfloat16_rn(f1);
    const __nv_bfloat16 l0 = __float2bfloat16_rn(f0 - __bfloat162float(h0));
    const __nv_bfloat16 l1 = __float2bfloat16_rn(f1 - __bfloat162float(h1));
    const int b = row >> 10, t = row & 1023;
    const size_t e2 = ((((size_t)b * 16 + h) * 1024 + t) * 64 + lane * 2) >> 1;
    __nv_bfloat16* dh = (which == 0 ? k1h : (which == 1 ? k2h : vhh));
    __nv_bfloat16* dl = (which == 0 ? k1l : (which == 1 ? k2l : vhl));
    ((__nv_bfloat162*)dh)[e2] = __nv_bfloat162(h0, h1);
    ((__nv_bfloat162*)dl)[e2] = __nv_bfloat162(l0, l1);
}

// ===========================================================================
// Flash attention with mma.sync bf16x3.
// Block: 128 q rows, 8 warps x 16 rows. Two passes (attn1, attn2).
// smem: Q stage (hi,lo) 128x72bf16 each; KV double-buffered stages of
// (Khi,Klo,Vhi,Vlo) 64x72bf16 tiles. Row stride 144B -> conflict-free ldmatrix.
// ===========================================================================
#define FSTR_B    144
#define FQ_TILE   (128 * FSTR_B)          // 18432
#define FKV_TILE  (64 * FSTR_B)           // 9216
#define FKV_STAGE (4 * FKV_TILE)          // 36864
#define FLASH_SMEM (2 * FQ_TILE + 2 * FKV_STAGE)   // 110592

__device__ __forceinline__ void flash_load_kv(
    uint32_t dst, const __nv_bfloat16* kh, const __nv_bfloat16* kl,
    const __nv_bfloat16* vh, const __nv_bfloat16* vl, int kt, int tid)
{
    const __nv_bfloat16* srcs[4] = {kh, kl, vh, vl};
    #pragma unroll
    for (int i = 0; i < 8; i++) {
        const int idx = tid + i * 256;
        const int t = idx >> 9;
        const int rem = idx & 511;
        const int row = rem >> 3, c = rem & 7;
        cp_async16(dst + t * FKV_TILE + row * FSTR_B + c * 16,
                   srcs[t] + ((size_t)(kt * 64 + row)) * HD_ + c * 8);
    }
}

__device__ __forceinline__ void flash_pass(
    const __nv_bfloat16* __restrict__ qh, const __nv_bfloat16* __restrict__ ql,
    const __nv_bfloat16* __restrict__ kh, const __nv_bfloat16* __restrict__ kl,
    const __nv_bfloat16* __restrict__ vh, const __nv_bfloat16* __restrict__ vl,
    int qt, int tid, uint32_t sQ, uint32_t sKV,
    float o[8][4], float m[2], float l[2])
{
    const int lane = tid & 31;
    const int w = tid >> 5;

    // stage Q (hi,lo) + KV tile 0
    #pragma unroll
    for (int i = 0; i < 8; i++) {
        const int idx = tid + i * 256;
        const int ts = idx >> 10;
        const int rem = idx & 1023;
        const int row = rem >> 3, c = rem & 7;
        cp_async16(sQ + ts * FQ_TILE + row * FSTR_B + c * 16,
                   (ts ? ql : qh) + ((size_t)(qt * 128 + row)) * HD_ + c * 8);
    }
    flash_load_kv(sKV, kh, kl, vh, vl, 0, tid);
    CP_COMMIT();
    flash_load_kv(sKV + FKV_STAGE, kh, kl, vh, vl, 1, tid);
    CP_COMMIT();

    CP_WAIT(1);
    __syncthreads();

    // Q fragments (register resident)
    uint32_t qhf[4][4], qlf[4][4];
    {
        const uint32_t qrow = (w * 16 + (lane & 15)) * FSTR_B + (lane >> 4) * 16;
        #pragma unroll
        for (int kc = 0; kc < 4; kc++) {
            ldsm_x4(qhf[kc][0], qhf[kc][1], qhf[kc][2], qhf[kc][3],
                    sQ + qrow + kc * 32);
            ldsm_x4(qlf[kc][0], qlf[kc][1], qlf[kc][2], qlf[kc][3],
                    sQ + FQ_TILE + qrow + kc * 32);
        }
    }

    const uint32_t lrow16 = (lane & 15) * FSTR_B + (lane >> 4) * 16;

    for (int t = 0; t < 16; t++) {
        if (t > 0) {
            if (t + 1 < 16) { CP_WAIT(1); } else { CP_WAIT(0); }
            __syncthreads();
        }
        const uint32_t st = sKV + (t & 1) * FKV_STAGE;

        // ---- S = Q K^T (bf16x3) ----
        float s[8][4];
        #pragma unroll
        for (int j = 0; j < 8; j++)
            #pragma unroll
            for (int q = 0; q < 4; q++) s[j][q] = 0.f;

        #pragma unroll
        for (int kc = 0; kc < 4; kc++) {
            #pragma unroll
            for (int g = 0; g < 4; g++) {
                const uint32_t addr = st + g * 16 * FSTR_B + lrow16 + kc * 32;
                uint32_t h0, h1, h2, h3, l0, l1, l2, l3;
                ldsm_x4(h0, h1, h2, h3, addr);
                ldsm_x4(l0, l1, l2, l3, addr + FKV_TILE);
                mma16816(s[2 * g],     qhf[kc], h0, h2);
                mma16816(s[2 * g],     qhf[kc], l0, l2);
                mma16816(s[2 * g],     qlf[kc], h0, h2);
                mma16816(s[2 * g + 1], qhf[kc], h1, h3);
                mma16816(s[2 * g + 1], qhf[kc], l1, l3);
                mma16816(s[2 * g + 1], qlf[kc], h1, h3);
            }
        }

        // ---- online softmax ----
        float mx0 = -1e30f, mx1 = -1e30f;
        #pragma unroll
        for (int j = 0; j < 8; j++) {
            mx0 = fmaxf(mx0, fmaxf(s[j][0], s[j][1]));
            mx1 = fmaxf(mx1, fmaxf(s[j][2], s[j][3]));
        }
        mx0 = fmaxf(mx0, __shfl_xor_sync(0xffffffffu, mx0, 1));
        mx0 = fmaxf(mx0, __shfl_xor_sync(0xffffffffu, mx0, 2));
        mx1 = fmaxf(mx1, __shfl_xor_sync(0xffffffffu, mx1, 1));
        mx1 = fmaxf(mx1, __shfl_xor_sync(0xffffffffu, mx1, 2));
        const float mn0 = fmaxf(m[0], mx0), mn1 = fmaxf(m[1], mx1);
        const float a0 = __expf(m[0] - mn0), a1 = __expf(m[1] - mn1);
        m[0] = mn0; m[1] = mn1;
        float ps0 = 0.f, ps1 = 0.f;
        #pragma unroll
        for (int j = 0; j < 8; j++) {
            s[j][0] = __expf(s[j][0] - mn0);
            s[j][1] = __expf(s[j][1] - mn0);
            s[j][2] = __expf(s[j][2] - mn1);
            s[j][3] = __expf(s[j][3] - mn1);
            ps0 += s[j][0] + s[j][1];
            ps1 += s[j][2] + s[j][3];
        }
        ps0 += __shfl_xor_sync(0xffffffffu, ps0, 1);
        ps0 += __shfl_xor_sync(0xffffffffu, ps0, 2);
        ps1 += __shfl_xor_sync(0xffffffffu, ps1, 1);
        ps1 += __shfl_xor_sync(0xffffffffu, ps1, 2);
        l[0] = l[0] * a0 + ps0;
        l[1] = l[1] * a1 + ps1;
        #pragma unroll
        for (int j = 0; j < 8; j++) {
            o[j][0] *= a0; o[j][1] *= a0;
            o[j][2] *= a1; o[j][3] *= a1;
        }

        // ---- P fragments (bf16 hi/lo) ----
        uint32_t ph[4][4], pl[4][4];
        #pragma unroll
        for (int kc = 0; kc < 4; kc++) {
            const int j0 = 2 * kc, j1 = 2 * kc + 1;
            ph[kc][0] = pack_bf16(s[j0][0], s[j0][1]);
            ph[kc][1] = pack_bf16(s[j0][2], s[j0][3]);
            ph[kc][2] = pack_bf16(s[j1][0], s[j1][1]);
            ph[kc][3] = pack_bf16(s[j1][2], s[j1][3]);
            float r00 = s[j0][0] - __bfloat162float(__float2bfloat16_rn(s[j0][0]));
            float r01 = s[j0][1] - __bfloat162float(__float2bfloat16_rn(s[j0][1]));
            float r02 = s[j0][2] - __bfloat162float(__float2bfloat16_rn(s[j0][2]));
            float r03 = s[j0][3] - __bfloat162float(__float2bfloat16_rn(s[j0][3]));
            float r10 = s[j1][0] - __bfloat162float(__float2bfloat16_rn(s[j1][0]));
            float r11 = s[j1][1] - __bfloat162float(__float2bfloat16_rn(s[j1][1]));
            float r12 = s[j1][2] - __bfloat162float(__float2bfloat16_rn(s[j1][2]));
            float r13 = s[j1][3] - __bfloat162float(__float2bfloat16_rn(s[j1][3]));
            pl[kc][0] = pack_bf16(r00, r01);
            pl[kc][1] = pack_bf16(r02, r03);
            pl[kc][2] = pack_bf16(r10, r11);
            pl[kc][3] = pack_bf16(r12, r13);
        }

        // ---- O += P V (bf16x3) ----
        #pragma unroll
        for (int kc = 0; kc < 4; kc++) {
            #pragma unroll
            for (int hg = 0; hg < 4; hg++) {
                const uint32_t addr = st + kc * 16 * FSTR_B + lrow16 + hg * 32;
                uint32_t vh0, vh1, vh2, vh3, vl0, vl1, vl2, vl3;
                ldsm_x4_t(vh0, vh1, vh2, vh3, addr + 2 * FKV_TILE);
                ldsm_x4_t(vl0, vl1, vl2, vl3, addr + 3 * FKV_TILE);
                mma16816(o[2 * hg],     ph[kc], vh0, vh1);
                mma16816(o[2 * hg],     pl[kc], vh0, vh1);
                mma16816(o[2 * hg],     ph[kc], vl0, vl1);
                mma16816(o[2 * hg + 1], ph[kc], vh2, vh3);
                mma16816(o[2 * hg + 1], pl[kc], vh2, vh3);
                mma16816(o[2 * hg + 1], ph[kc], vl2, vl3);
            }
        }

        __syncthreads();
        if (t + 2 < 16) {
            flash_load_kv(st, kh, kl, vh, vl, t + 2, tid);
            CP_COMMIT();
        }
    }
}

__global__ __launch_bounds__(256, 1) void flash_mma_kernel(
    const __nv_bfloat16* __restrict__ q1h, const __nv_bfloat16* __restrict__ q1l,
    const __nv_bfloat16* __restrict__ q2h, const __nv_bfloat16* __restrict__ q2l,
    const __nv_bfloat16* __restrict__ k1h, const __nv_bfloat16* __restrict__ k1l,
    const __nv_bfloat16* __restrict__ k2h, const __nv_bfloat16* __restrict__ k2l,
    const __nv_bfloat16* __restrict__ vhh, const __nv_bfloat16* __restrict__ vhl,
    const float* __restrict__ lmb, float* __restrict__ y)
{
    extern __shared__ __align__(128) char smem[];
    const uint32_t sb = smem_to_u32(smem);
    const uint32_t sQ = sb, sKV = sb + 2 * FQ_TILE;
    const int tid = threadIdx.x;
    const int qt = blockIdx.x, h = blockIdx.y, b = blockIdx.z;
    const int bh = b * H_ + h;
    const size_t off = (size_t)bh * TQ_ * HD_;

    float o1[8][4];
    float m1[2] = {-1e30f, -1e30f}, l1[2] = {0.f, 0.f};
    #pragma unroll
    for (int j = 0; j < 8; j++)
        #pragma unroll
        for (int q = 0; q < 4; q++) o1[j][q] = 0.f;

    flash_pass(q1h + off, q1l + off, k1h + off, k1l + off, vhh + off, vhl + off,
               qt, tid, sQ, sKV, o1, m1, l1);
    __syncthreads();

    float o2[8][4];
    float m2[2] = {-1e30f, -1e30f}, l2[2] = {0.f, 0.f};
    #pragma unroll
    for (int j = 0; j < 8; j++)
        #pragma unroll
        for (int q = 0; q < 4; q++) o2[j][q] = 0.f;

    flash_pass(q2h + off, q2l + off, k2h + off, k2l + off, vhh + off, vhl + off,
               qt, tid, sQ, sKV, o2, m2, l2);

    // epilogue
    const float cmul = log1pf(__expf(lmb[h]));
    const int lane = tid & 31, w = tid >> 5;
    const int r0 = lane >> 2, cb = (lane & 3) * 2;
    const float il10 = 1.f / l1[0], il11 = 1.f / l1[1];
    const float il20 = cmul / l2[0], il21 = cmul / l2[1];
    const size_t ybase = off + (size_t)(qt * 128 + w * 16) * HD_;
    #pragma unroll
    for (int j = 0; j < 8; j++) {
        float2 v0 = make_float2(o1[j][0] * il10 - o2[j][0] * il20,
                                o1[j][1] * il10 - o2[j][1] * il20);
        float2 v1 = make_float2(o1[j][2] * il11 - o2[j][2] * il21,
                                o1[j][3] * il11 - o2[j][3] * il21);
        *(float2*)&y[ybase + (size_t)r0 * HD_ + j * 8 + cb]       = v0;
        *(float2*)&y[ybase + (size_t)(r0 + 8) * HD_ + j * 8 + cb] = v1;
    }
}

// ===========================================================================
// GroupNorm stats
// ===========================================================================
__global__ void gn_stats_kernel(const float* __restrict__ y, float* __restrict__ stats)
{
    __shared__ float rs[256], rq[256];
    const int bh = blockIdx.x, tid = threadIdx.x;
    const float* p = y + (size_t)bh * TQ_ * HD_;
    float s = 0.f, q = 0.f;
    for (int i = tid * 4; i < TQ_ * HD_; i += 256 * 4) {
        float4 v = *(const float4*)(p + i);
        s += v.x + v.y + v.z + v.w;
        q += v.x * v.x + v.y * v.y + v.z * v.z + v.w * v.w;
    }
    rs[tid] = s; rq[tid] = q;
    __syncthreads();
    for (int o = 128; o; o >>= 1) {
        if (tid < o) { rs[tid] += rs[tid + o]; rq[tid] += rq[tid + o]; }
        __syncthreads();
    }
    if (tid == 0) {
        const float inv = 1.f / (float)(TQ_ * HD_);
        const float mu = rs[0] * inv;
        const float var = rq[0] * inv - mu * mu;
        stats[bh * 2 + 0] = mu;
        stats[bh * 2 + 1] = rsqrtf(var + EPS_);
    }
}

// ===========================================================================
// GroupNorm apply + transpose + bf16 hi/lo split
// ===========================================================================
__global__ void gn_apply_kernel(const float* __restrict__ y, const float* __restrict__ stats,
                                const float* __restrict__ gw, const float* __restrict__ gb,
                                __nv_bfloat16* __restrict__ hi, __nv_bfloat16* __restrict__ lo)
{
    const int i4 = blockIdx.x * blockDim.x + threadIdx.x;
    const int d4 = i4 & 255;
    const int t  = (i4 >> 8) & 1023;
    const int b  = i4 >> 18;
    const int c  = d4 * 4;
    const int h  = c >> 6;
    const int dd = c & 63;
    const float mu   = stats[(b * 16 + h) * 2 + 0];
    const float rstd = stats[(b * 16 + h) * 2 + 1];
    float4 v = *(const float4*)&y[(((size_t)(b * 16 + h)) * 1024 + t) * 64 + dd];
    float4 w = *(const float4*)&gw[c];
    float4 bb = *(const float4*)&gb[c];
    float f[4];
    f[0] = (v.x - mu) * rstd * w.x + bb.x;
    f[1] = (v.y - mu) * rstd * w.y + bb.y;
    f[2] = (v.z - mu) * rstd * w.z + bb.z;
    f[3] = (v.w - mu) * rstd * w.w + bb.w;
    __nv_bfloat16 hb[4], lb[4];
    #pragma unroll
    for (int j = 0; j < 4; j++) {
        hb[j] = __float2bfloat16_rn(f[j]);
        lb[j] = __float2bfloat16_rn(f[j] - __bfloat162float(hb[j]));
    }
    ((__nv_bfloat162*)hi)[2*i4 + 0] = __nv_bfloat162(hb[0], hb[1]);
    ((__nv_bfloat162*)hi)[2*i4 + 1] = __nv_bfloat162(hb[2], hb[3]);
    ((__nv_bfloat162*)lo)[2*i4 + 0] = __nv_bfloat162(lb[0], lb[1]);
    ((__nv_bfloat162*)lo)[2*i4 + 1] = __nv_bfloat162(lb[2], lb[3]);
}

// ===========================================================================
// Launch
// ===========================================================================
extern "C" void kernel_launch(void* const* d_in, const int* in_sizes, int n_in,
                              void* d_out, int out_size)
{
    const float* x_q  = (const float*)d_in[0];
    const float* x_kv = (const float*)d_in[1];
    const float* Wq   = (const float*)d_in[2];
    const float* Wkv  = (const float*)d_in[3];
    const float* Wc   = (const float*)d_in[4];
    const float* qn1  = (const float*)d_in[5];
    const float* kn1  = (const float*)d_in[6];
    const float* qn2  = (const float*)d_in[7];
    const float* kn2  = (const float*)d_in[8];
    const float* gn_w = (const float*)d_in[9];
    const float* gn_b = (const float*)d_in[10];
    const float* lmb  = (const float*)d_in[11];
    float* out = (float*)d_out;

    float *qproj, *kvproj, *y, *stats;
    cudaGetSymbolAddress((void**)&qproj,  g_qproj);
    cudaGetSymbolAddress((void**)&kvproj, g_kvproj);
    cudaGetSymbolAddress((void**)&y,      g_y);
    cudaGetSymbolAddress((void**)&stats,  g_stats);

    __nv_bfloat16 *xq_hi, *xq_lo, *xkv_hi, *xkv_lo;
    __nv_bfloat16 *wqt_hi, *wqt_lo, *wkvt_hi, *wkvt_lo, *wct_hi, *wct_lo;
    __nv_bfloat16 *ybt_hi, *ybt_lo;
    __nv_bfloat16 *q1h, *q1l, *q2h, *q2l, *k1h, *k1l, *k2h, *k2l, *vhh, *vhl;
    cudaGetSymbolAddress((void**)&xq_hi,   g_xq_hi);
    cudaGetSymbolAddress((void**)&xq_lo,   g_xq_lo);
    cudaGetSymbolAddress((void**)&xkv_hi,  g_xkv_hi);
    cudaGetSymbolAddress((void**)&xkv_lo,  g_xkv_lo);
    cudaGetSymbolAddress((void**)&wqt_hi,  g_wqt_hi);
    cudaGetSymbolAddress((void**)&wqt_lo,  g_wqt_lo);
    cudaGetSymbolAddress((void**)&wkvt_hi, g_wkvt_hi);
    cudaGetSymbolAddress((void**)&wkvt_lo, g_wkvt_lo);
    cudaGetSymbolAddress((void**)&wct_hi,  g_wct_hi);
    cudaGetSymbolAddress((void**)&wct_lo,  g_wct_lo);
    cudaGetSymbolAddress((void**)&ybt_hi,  g_ybt_hi);
    cudaGetSymbolAddress((void**)&ybt_lo,  g_ybt_lo);
    cudaGetSymbolAddress((void**)&q1h, g_q1h);
    cudaGetSymbolAddress((void**)&q1l, g_q1l);
    cudaGetSymbolAddress((void**)&q2h, g_q2h);
    cudaGetSymbolAddress((void**)&q2l, g_q2l);
    cudaGetSymbolAddress((void**)&k1h, g_k1h);
    cudaGetSymbolAddress((void**)&k1l, g_k1l);
    cudaGetSymbolAddress((void**)&k2h, g_k2h);
    cudaGetSymbolAddress((void**)&k2l, g_k2l);
    cudaGetSymbolAddress((void**)&vhh, g_vhh);
    cudaGetSymbolAddress((void**)&vhl, g_vhl);

    const int M = B_ * TQ_;  // 4096

    cudaFuncSetAttribute(gemm_mma, cudaFuncAttributeMaxDynamicSharedMemorySize, GM_SMEM);
    cudaFuncSetAttribute(flash_mma_kernel, cudaFuncAttributeMaxDynamicSharedMemorySize, FLASH_SMEM);

    // 0) split/convert operands to bf16 hi/lo
    {
        const int n4 = M * D_ / 4;
        split_kernel<<<n4 / 256, 256>>>(x_q,  xq_hi,  xq_lo,  n4);
        split_kernel<<<n4 / 256, 256>>>(x_kv, xkv_hi, xkv_lo, n4);
        split_transpose_kernel<<<dim3(2 * D_ / 32, D_ / 32), dim3(32, 8)>>>(Wq,  wqt_hi,  wqt_lo,  D_, 2 * D_);
        split_transpose_kernel<<<dim3(3 * D_ / 32, D_ / 32), dim3(32, 8)>>>(Wkv, wkvt_hi, wkvt_lo, D_, 3 * D_);
        split_transpose_kernel<<<dim3(D_ / 32, D_ / 32),     dim3(32, 8)>>>(Wc,  wct_hi,  wct_lo,  D_, D_);
    }

    // 1) projections (mma.sync bf16x3)
    gemm_mma<<<dim3(2 * D_ / 128, M / 128), 256, GM_SMEM>>>(xq_hi,  xq_lo,  wqt_hi,  wqt_lo,  qproj,  M, 2 * D_, D_);
    gemm_mma<<<dim3(3 * D_ / 128, M / 128), 256, GM_SMEM>>>(xkv_hi, xkv_lo, wkvt_hi, wkvt_lo, kvproj, M, 3 * D_, D_);

    // 2) RMSNorm + head reshape + bf16 hi/lo split
    rms_q_kernel<<<M * H_ * 2 * 32 / 256, 256>>>(qproj, qn1, qn2, q1h, q1l, q2h, q2l);
    rms_kv_kernel<<<M * H_ * 3 * 32 / 256, 256>>>(kvproj, kn1, kn2, k1h, k1l, k2h, k2l, vhh, vhl);

    // 3) fused dual flash attention (mma.sync bf16x3)
    flash_mma_kernel<<<dim3(TQ_ / 128, H_, B_), 256, FLASH_SMEM>>>(
        q1h, q1l, q2h, q2l, k1h, k1l, k2h, k2l, vhh, vhl, lmb, y);

    // 4) GroupNorm
    gn_stats_kernel<<<B_ * H_, 256>>>(y, stats);
    gn_apply_kernel<<<(B_ * TQ_ * D_ / 4) / 256, 256>>>(y, stats, gn_w, gn_b, ybt_hi, ybt_lo);

    // 5) output projection (mma.sync bf16x3)
    gemm_mma<<<dim3(D_ / 128, M / 128), 256, GM_SMEM>>>(ybt_hi, ybt_lo, wct_hi, wct_lo, out, M, D_, D_);
}

// round 8
// speedup vs baseline: 2.3347x; 1.0296x over previous
#include <cuda_runtime.h>
#include <cuda_bf16.h>
#include <math.h>
#include <stdint.h>

// Problem constants
#define B_    4
#define TQ_   1024
#define TKV_  1024
#define D_    1024
#define H_    16
#define HD_   64
#define EPS_  1e-5f

// ===========================================================================
// PTX helpers (baseline features only — compute_103 virtual arch safe)
// ===========================================================================
__device__ __forceinline__ uint32_t smem_to_u32(const void* smem_ptr) {
    uint32_t addr;
    asm("{ .reg .u64 tmp; cvta.to.shared.u64 tmp, %1; cvt.u32.u64 %0, tmp; }"
        : "=r"(addr) : "l"(smem_ptr));
    return addr;
}

__device__ __forceinline__ void cp_async16(uint32_t dst, const void* src) {
    asm volatile("cp.async.cg.shared.global [%0], [%1], 16;" :: "r"(dst), "l"(src));
}
#define CP_COMMIT() asm volatile("cp.async.commit_group;" ::: "memory")
#define CP_WAIT(n)  asm volatile("cp.async.wait_group %0;" :: "n"(n) : "memory")

__device__ __forceinline__ void ldsm_x4(uint32_t& r0, uint32_t& r1, uint32_t& r2,
                                        uint32_t& r3, uint32_t addr) {
    asm volatile("ldmatrix.sync.aligned.m8n8.x4.shared.b16 {%0,%1,%2,%3}, [%4];"
        : "=r"(r0), "=r"(r1), "=r"(r2), "=r"(r3) : "r"(addr));
}

__device__ __forceinline__ void ldsm_x4_t(uint32_t& r0, uint32_t& r1, uint32_t& r2,
                                          uint32_t& r3, uint32_t addr) {
    asm volatile("ldmatrix.sync.aligned.m8n8.x4.trans.shared.b16 {%0,%1,%2,%3}, [%4];"
        : "=r"(r0), "=r"(r1), "=r"(r2), "=r"(r3) : "r"(addr));
}

// D += A * B  (m16n8k16, bf16 inputs, fp32 accum)
__device__ __forceinline__ void mma16816(float* d, const uint32_t* a,
                                         uint32_t b0, uint32_t b1) {
    asm volatile(
        "mma.sync.aligned.m16n8k16.row.col.f32.bf16.bf16.f32 "
        "{%0,%1,%2,%3}, {%4,%5,%6,%7}, {%8,%9}, {%0,%1,%2,%3};"
        : "+f"(d[0]), "+f"(d[1]), "+f"(d[2]), "+f"(d[3])
        : "r"(a[0]), "r"(a[1]), "r"(a[2]), "r"(a[3]), "r"(b0), "r"(b1));
}

__device__ __forceinline__ uint32_t pack_bf16(float a, float b) {
    __nv_bfloat162 t = __floats2bfloat162_rn(a, b);
    return *reinterpret_cast<uint32_t*>(&t);
}

// ===========================================================================
// Device scratch
// ===========================================================================
__device__ float g_qproj [B_ * TQ_  * 2 * D_];
__device__ float g_kvproj[B_ * TKV_ * 3 * D_];
__device__ float g_y     [B_ * H_ * TQ_  * HD_];
__device__ float g_stats [B_ * H_ * 2];

__device__ __nv_bfloat16 g_xq_hi [B_ * TQ_ * D_];
__device__ __nv_bfloat16 g_xq_lo [B_ * TQ_ * D_];
__device__ __nv_bfloat16 g_xkv_hi[B_ * TKV_ * D_];
__device__ __nv_bfloat16 g_xkv_lo[B_ * TKV_ * D_];
__device__ __nv_bfloat16 g_wqt_hi [2 * D_ * D_];
__device__ __nv_bfloat16 g_wqt_lo [2 * D_ * D_];
__device__ __nv_bfloat16 g_wkvt_hi[3 * D_ * D_];
__device__ __nv_bfloat16 g_wkvt_lo[3 * D_ * D_];
__device__ __nv_bfloat16 g_wct_hi [D_ * D_];
__device__ __nv_bfloat16 g_wct_lo [D_ * D_];
__device__ __nv_bfloat16 g_ybt_hi [B_ * TQ_ * D_];
__device__ __nv_bfloat16 g_ybt_lo [B_ * TQ_ * D_];

// bf16 hi/lo attention operands, (B,H,T,HD)
__device__ __nv_bfloat16 g_q1h[B_ * H_ * TQ_ * HD_];
__device__ __nv_bfloat16 g_q1l[B_ * H_ * TQ_ * HD_];
__device__ __nv_bfloat16 g_q2h[B_ * H_ * TQ_ * HD_];
__device__ __nv_bfloat16 g_q2l[B_ * H_ * TQ_ * HD_];
__device__ __nv_bfloat16 g_k1h[B_ * H_ * TKV_ * HD_];
__device__ __nv_bfloat16 g_k1l[B_ * H_ * TKV_ * HD_];
__device__ __nv_bfloat16 g_k2h[B_ * H_ * TKV_ * HD_];
__device__ __nv_bfloat16 g_k2l[B_ * H_ * TKV_ * HD_];
__device__ __nv_bfloat16 g_vhh[B_ * H_ * TKV_ * HD_];
__device__ __nv_bfloat16 g_vhl[B_ * H_ * TKV_ * HD_];

// ===========================================================================
// Split fp32 -> bf16 hi/lo
// ===========================================================================
__global__ void split_kernel(const float* __restrict__ x,
                             __nv_bfloat16* __restrict__ hi,
                             __nv_bfloat16* __restrict__ lo, int n4)
{
    const int i = blockIdx.x * blockDim.x + threadIdx.x;
    if (i >= n4) return;
    float4 v = ((const float4*)x)[i];
    float f[4] = {v.x, v.y, v.z, v.w};
    __nv_bfloat16 h[4], l[4];
    #pragma unroll
    for (int j = 0; j < 4; j++) {
        h[j] = __float2bfloat16_rn(f[j]);
        l[j] = __float2bfloat16_rn(f[j] - __bfloat162float(h[j]));
    }
    ((__nv_bfloat162*)hi)[2*i + 0] = __nv_bfloat162(h[0], h[1]);
    ((__nv_bfloat162*)hi)[2*i + 1] = __nv_bfloat162(h[2], h[3]);
    ((__nv_bfloat162*)lo)[2*i + 0] = __nv_bfloat162(l[0], l[1]);
    ((__nv_bfloat162*)lo)[2*i + 1] = __nv_bfloat162(l[2], l[3]);
}

// ===========================================================================
// Transpose + split: W [K,N] fp32 -> Wt_hi/lo [N,K] bf16 (K-major)
// ===========================================================================
__global__ void split_transpose_kernel(const float* __restrict__ W,
                                       __nv_bfloat16* __restrict__ hi,
                                       __nv_bfloat16* __restrict__ lo, int K, int N)
{
    __shared__ float t[32][33];
    const int n0 = blockIdx.x * 32, k0 = blockIdx.y * 32;
    #pragma unroll
    for (int dy = 0; dy < 32; dy += 8)
        t[threadIdx.y + dy][threadIdx.x] =
            W[(size_t)(k0 + threadIdx.y + dy) * N + n0 + threadIdx.x];
    __syncthreads();
    #pragma unroll
    for (int dy = 0; dy < 32; dy += 8) {
        const int n = n0 + threadIdx.y + dy, k = k0 + threadIdx.x;
        const float v = t[threadIdx.x][threadIdx.y + dy];
        const __nv_bfloat16 h = __float2bfloat16_rn(v);
        hi[(size_t)n * K + k] = h;
        lo[(size_t)n * K + k] = __float2bfloat16_rn(v - __bfloat162float(h));
    }
}

// ===========================================================================
// mma.sync bf16x3 GEMM (unchanged from passing round)
// ===========================================================================
#define SAST       40
#define GM_TILE_B  (128 * SAST * 2)
#define GM_STAGE_B (4 * GM_TILE_B)
#define GM_SMEM    (2 * GM_STAGE_B)

__device__ __forceinline__ void gm_load_stage(
    uint32_t stage_base, const __nv_bfloat16* const* srcs, int k0, int K, int tid)
{
    #pragma unroll
    for (int t = 0; t < 4; t++) {
        const __nv_bfloat16* s = srcs[t] + k0;
        const uint32_t tb = stage_base + t * GM_TILE_B;
        #pragma unroll
        for (int i = 0; i < 2; i++) {
            const int idx = tid + i * 256;
            const int row = idx >> 2, c16 = idx & 3;
            cp_async16(tb + row * (SAST * 2) + c16 * 16,
                       s + (size_t)row * K + c16 * 8);
        }
    }
    CP_COMMIT();
}

__global__ __launch_bounds__(256) void gemm_mma(
    const __nv_bfloat16* __restrict__ Ahi, const __nv_bfloat16* __restrict__ Alo,
    const __nv_bfloat16* __restrict__ Bhi, const __nv_bfloat16* __restrict__ Blo,
    float* __restrict__ C, int M, int N, int K)
{
    extern __shared__ __align__(128) char smem[];
    const uint32_t sb = smem_to_u32(smem);
    const int tid = threadIdx.x;
    const int lane = tid & 31;
    const int wid = tid >> 5;
    const int wm = wid & 1;
    const int wn = wid >> 1;
    const int bx = blockIdx.x, by = blockIdx.y;

    const __nv_bfloat16* srcs[4] = {
        Ahi + (size_t)(by * 128) * K, Alo + (size_t)(by * 128) * K,
        Bhi + (size_t)(bx * 128) * K, Blo + (size_t)(bx * 128) * K };

    float acc[4][4][4];
    #pragma unroll
    for (int a = 0; a < 4; a++)
        #pragma unroll
        for (int b = 0; b < 4; b++)
            #pragma unroll
            for (int c = 0; c < 4; c++) acc[a][b][c] = 0.f;

    const int nch = K >> 5;
    gm_load_stage(sb, srcs, 0, K, tid);

    const uint32_t lrow = (lane & 15);
    const uint32_t lcol16 = (lane >> 4) * 16;

    for (int c = 0; c < nch; c++) {
        if (c + 1 < nch) gm_load_stage(sb + ((c + 1) & 1) * GM_STAGE_B, srcs, (c + 1) << 5, K, tid);
        if (c + 1 < nch) { CP_WAIT(1); } else { CP_WAIT(0); }
        __syncthreads();

        const uint32_t st = sb + (c & 1) * GM_STAGE_B;
        #pragma unroll
        for (int ks = 0; ks < 2; ks++) {
            const uint32_t coff = lcol16 + ks * 32;
            uint32_t bh[2][4], bl[2][4];
            #pragma unroll
            for (int nt = 0; nt < 2; nt++) {
                const uint32_t baddr = st + 2 * GM_TILE_B
                    + (wn * 32 + nt * 16 + lrow) * (SAST * 2) + coff;
                ldsm_x4(bh[nt][0], bh[nt][1], bh[nt][2], bh[nt][3], baddr);
                ldsm_x4(bl[nt][0], bl[nt][1], bl[nt][2], bl[nt][3], baddr + GM_TILE_B);
            }
            #pragma unroll
            for (int mt = 0; mt < 4; mt++) {
                const uint32_t aaddr = st
                    + (wm * 64 + mt * 16 + lrow) * (SAST * 2) + coff;
                uint32_t ah[4], al[4];
                ldsm_x4(ah[0], ah[1], ah[2], ah[3], aaddr);
                ldsm_x4(al[0], al[1], al[2], al[3], aaddr + GM_TILE_B);
                #pragma unroll
                for (int nt = 0; nt < 2; nt++) {
                    #pragma unroll
                    for (int hh = 0; hh < 2; hh++) {
                        float* d = acc[mt][nt * 2 + hh];
                        uint32_t bfh0 = bh[nt][hh], bfh1 = bh[nt][hh + 2];
                        mma16816(d, ah, bfh0, bfh1);
                        mma16816(d, ah, bl[nt][hh], bl[nt][hh + 2]);
                        mma16816(d, al, bfh0, bfh1);
                    }
                }
            }
        }
        __syncthreads();
    }

    #pragma unroll
    for (int mt = 0; mt < 4; mt++) {
        const int row0 = by * 128 + wm * 64 + mt * 16 + (lane >> 2);
        #pragma unroll
        for (int n8 = 0; n8 < 4; n8++) {
            const int col = bx * 128 + wn * 32 + n8 * 8 + (lane & 3) * 2;
            float2 o0 = make_float2(acc[mt][n8][0], acc[mt][n8][1]);
            float2 o1 = make_float2(acc[mt][n8][2], acc[mt][n8][3]);
            *(float2*)&C[(size_t)row0 * N + col]       = o0;
            *(float2*)&C[(size_t)(row0 + 8) * N + col] = o1;
        }
    }
}

// ===========================================================================
// RMSNorm + head split for Q -> bf16 hi/lo, prescaled by 1/8
// ===========================================================================
__global__ void rms_q_kernel(const float* __restrict__ qp,
                             const float* __restrict__ qn1, const float* __restrict__ qn2,
                             __nv_bfloat16* __restrict__ q1h, __nv_bfloat16* __restrict__ q1l,
                             __nv_bfloat16* __restrict__ q2h, __nv_bfloat16* __restrict__ q2l)
{
    const int gw   = (blockIdx.x * blockDim.x + threadIdx.x) >> 5;
    const int lane = threadIdx.x & 31;
    const int which = gw & 1;
    const int h     = (gw >> 1) & 15;
    const int row   = gw >> 5;
    const float* src = qp + (size_t)row * 2048 + which * 1024 + h * 64 + lane * 2;
    float2 v = *(const float2*)src;
    float ss = v.x * v.x + v.y * v.y;
    #pragma unroll
    for (int o = 16; o; o >>= 1) ss += __shfl_xor_sync(0xffffffffu, ss, o);
    const float r = rsqrtf(ss * (1.0f / 64.0f) + EPS_);
    const int b = row >> 10, t = row & 1023;
    const float* w = (which ? qn2 : qn1) + lane * 2;
    const float f0 = v.x * r * w[0] * 0.125f;
    const float f1 = v.y * r * w[1] * 0.125f;
    const __nv_bfloat16 h0 = __float2bfloat16_rn(f0);
    const __nv_bfloat16 h1 = __float2bfloat16_rn(f1);
    const __nv_bfloat16 l0 = __float2bfloat16_rn(f0 - __bfloat162float(h0));
    const __nv_bfloat16 l1 = __float2bfloat16_rn(f1 - __bfloat162float(h1));
    const size_t e2 = ((((size_t)b * 16 + h) * 1024 + t) * 64 + lane * 2) >> 1;
    __nv_bfloat16* dh = which ? q2h : q1h;
    __nv_bfloat16* dl = which ? q2l : q1l;
    ((__nv_bfloat162*)dh)[e2] = __nv_bfloat162(h0, h1);
    ((__nv_bfloat162*)dl)[e2] = __nv_bfloat162(l0, l1);
}

// ===========================================================================
// RMSNorm + head split for KV -> bf16 hi/lo
// ===========================================================================
__global__ void rms_kv_kernel(const float* __restrict__ kvp,
                              const float* __restrict__ kn1, const float* __restrict__ kn2,
                              __nv_bfloat16* __restrict__ k1h, __nv_bfloat16* __restrict__ k1l,
                              __nv_bfloat16* __restrict__ k2h, __nv_bfloat16* __restrict__ k2l,
                              __nv_bfloat16* __restrict__ vhh, __nv_bfloat16* __restrict__ vhl)
{
    const int gw   = (blockIdx.x * blockDim.x + threadIdx.x) >> 5;
    const int lane = threadIdx.x & 31;
    const int which = gw % 3;
    const int rh    = gw / 3;
    const int h     = rh & 15;
    const int row   = rh >> 4;
    const float* src = kvp + (size_t)row * 3072 + which * 1024 + h * 64 + lane * 2;
    float2 v = *(const float2*)src;
    float r = 1.0f;
    float w0 = 1.0f, w1 = 1.0f;
    if (which < 2) {
        float ss = v.x * v.x + v.y * v.y;
        #pragma unroll
        for (int o = 16; o; o >>= 1) ss += __shfl_xor_sync(0xffffffffu, ss, o);
        r = rsqrtf(ss * (1.0f / 64.0f) + EPS_);
        const float* w = (which ? kn2 : kn1) + lane * 2;
        w0 = w[0]; w1 = w[1];
    }
    const float f0 = v.x * r * w0;
    const float f1 = v.y * r * w1;
    const __nv_bfloat16 h0 = __float2bfloat16_rn(f0);
    const __nv_bfloat16 h1 = __float2bfloat16_rn(f1);
    const __nv_bfloat16 l0 = __float2bfloat16_rn(f0 - __bfloat162float(h0));
    const __nv_bfloat16 l1 = __float2bfloat16_rn(f1 - __bfloat162float(h1));
    const int b = row >> 10, t = row & 1023;
    const size_t e2 = ((((size_t)b * 16 + h) * 1024 + t) * 64 + lane * 2) >> 1;
    __nv_bfloat16* dh = (which == 0 ? k1h : (which == 1 ? k2h : vhh));
    __nv_bfloat16* dl = (which == 0 ? k1l : (which == 1 ? k2l : vhl));
    ((__nv_bfloat162*)dh)[e2] = __nv_bfloat162(h0, h1);
    ((__nv_bfloat162*)dl)[e2] = __nv_bfloat162(l0, l1);
}

// ===========================================================================
// MERGED dual flash attention with mma.sync bf16x3.
// Block: 128 q rows, 8 warps x 16 rows. ONE pass over kv; both attentions
// processed per tile (V loaded once). Q1 frags register-resident; Q2 frags
// re-ldmatrix'd per tile to cap register pressure.
// smem: 4 Q tiles (Q1h,Q1l,Q2h,Q2l) + double-buffered 6-tile KV stages
// (K1h,K1l,K2h,K2l,Vh,Vl). Row stride 144B -> conflict-free ldmatrix.
// ===========================================================================
#define FSTR_B    144
#define FQ_TILE   (128 * FSTR_B)            // 18432
#define FKV_TILE  (64 * FSTR_B)             // 9216
#define FKV_STAGE (6 * FKV_TILE)            // 55296
#define FLASH_SMEM (4 * FQ_TILE + 2 * FKV_STAGE)   // 184320

__device__ __forceinline__ void flash_load_kv6(
    uint32_t dst, const __nv_bfloat16* const* srcs, int kt, int tid)
{
    #pragma unroll
    for (int i = 0; i < 12; i++) {
        const int idx = tid + i * 256;          // 3072 chunks of 16B
        const int t = idx >> 9;
        const int rem = idx & 511;
        const int row = rem >> 3, c = rem & 7;
        cp_async16(dst + t * FKV_TILE + row * FSTR_B + c * 16,
                   srcs[t] + ((size_t)(kt * 64 + row)) * HD_ + c * 8);
    }
}

// online softmax update on S fragments; scales o, updates m/l, returns exp'd s
__device__ __forceinline__ void softmax_step(float s[8][4], float m[2], float l[2],
                                             float o[8][4])
{
    float mx0 = -1e30f, mx1 = -1e30f;
    #pragma unroll
    for (int j = 0; j < 8; j++) {
        mx0 = fmaxf(mx0, fmaxf(s[j][0], s[j][1]));
        mx1 = fmaxf(mx1, fmaxf(s[j][2], s[j][3]));
    }
    mx0 = fmaxf(mx0, __shfl_xor_sync(0xffffffffu, mx0, 1));
    mx0 = fmaxf(mx0, __shfl_xor_sync(0xffffffffu, mx0, 2));
    mx1 = fmaxf(mx1, __shfl_xor_sync(0xffffffffu, mx1, 1));
    mx1 = fmaxf(mx1, __shfl_xor_sync(0xffffffffu, mx1, 2));
    const float mn0 = fmaxf(m[0], mx0), mn1 = fmaxf(m[1], mx1);
    const float a0 = __expf(m[0] - mn0), a1 = __expf(m[1] - mn1);
    m[0] = mn0; m[1] = mn1;
    float ps0 = 0.f, ps1 = 0.f;
    #pragma unroll
    for (int j = 0; j < 8; j++) {
        s[j][0] = __expf(s[j][0] - mn0);
        s[j][1] = __expf(s[j][1] - mn0);
        s[j][2] = __expf(s[j][2] - mn1);
        s[j][3] = __expf(s[j][3] - mn1);
        ps0 += s[j][0] + s[j][1];
        ps1 += s[j][2] + s[j][3];
    }
    ps0 += __shfl_xor_sync(0xffffffffu, ps0, 1);
    ps0 += __shfl_xor_sync(0xffffffffu, ps0, 2);
    ps1 += __shfl_xor_sync(0xffffffffu, ps1, 1);
    ps1 += __shfl_xor_sync(0xffffffffu, ps1, 2);
    l[0] = l[0] * a0 + ps0;
    l[1] = l[1] * a1 + ps1;
    #pragma unroll
    for (int j = 0; j < 8; j++) {
        o[j][0] *= a0; o[j][1] *= a0;
        o[j][2] *= a1; o[j][3] *= a1;
    }
}

// build P hi/lo fragments from exp'd s
__device__ __forceinline__ void build_p(const float s[8][4],
                                        uint32_t ph[4][4], uint32_t pl[4][4])
{
    #pragma unroll
    for (int kc = 0; kc < 4; kc++) {
        const int j0 = 2 * kc, j1 = 2 * kc + 1;
        ph[kc][0] = pack_bf16(s[j0][0], s[j0][1]);
        ph[kc][1] = pack_bf16(s[j0][2], s[j0][3]);
        ph[kc][2] = pack_bf16(s[j1][0], s[j1][1]);
        ph[kc][3] = pack_bf16(s[j1][2], s[j1][3]);
        float r00 = s[j0][0] - __bfloat162float(__float2bfloat16_rn(s[j0][0]));
        float r01 = s[j0][1] - __bfloat162float(__float2bfloat16_rn(s[j0][1]));
        float r02 = s[j0][2] - __bfloat162float(__float2bfloat16_rn(s[j0][2]));
        float r03 = s[j0][3] - __bfloat162float(__float2bfloat16_rn(s[j0][3]));
        float r10 = s[j1][0] - __bfloat162float(__float2bfloat16_rn(s[j1][0]));
        float r11 = s[j1][1] - __bfloat162float(__float2bfloat16_rn(s[j1][1]));
        float r12 = s[j1][2] - __bfloat162float(__float2bfloat16_rn(s[j1][2]));
        float r13 = s[j1][3] - __bfloat162float(__float2bfloat16_rn(s[j1][3]));
        pl[kc][0] = pack_bf16(r00, r01);
        pl[kc][1] = pack_bf16(r02, r03);
        pl[kc][2] = pack_bf16(r10, r11);
        pl[kc][3] = pack_bf16(r12, r13);
    }
}

// O += P V (bf16x3), V tiles at voff_h / voff_h + FKV_TILE
__device__ __forceinline__ void pv_step(float o[8][4], const uint32_t ph[4][4],
                                        const uint32_t pl[4][4], uint32_t st,
                                        uint32_t lrow16)
{
    #pragma unroll
    for (int kc = 0; kc < 4; kc++) {
        #pragma unroll
        for (int hg = 0; hg < 4; hg++) {
            const uint32_t addr = st + kc * 16 * FSTR_B + lrow16 + hg * 32;
            uint32_t vh0, vh1, vh2, vh3, vl0, vl1, vl2, vl3;
            ldsm_x4_t(vh0, vh1, vh2, vh3, addr + 4 * FKV_TILE);
            ldsm_x4_t(vl0, vl1, vl2, vl3, addr + 5 * FKV_TILE);
            mma16816(o[2 * hg],     ph[kc], vh0, vh1);
            mma16816(o[2 * hg],     pl[kc], vh0, vh1);
            mma16816(o[2 * hg],     ph[kc], vl0, vl1);
            mma16816(o[2 * hg + 1], ph[kc], vh2, vh3);
            mma16816(o[2 * hg + 1], pl[kc], vh2, vh3);
            mma16816(o[2 * hg + 1], ph[kc], vl2, vl3);
        }
    }
}

__global__ __launch_bounds__(256, 1) void flash_mma_kernel(
    const __nv_bfloat16* __restrict__ q1h, const __nv_bfloat16* __restrict__ q1l,
    const __nv_bfloat16* __restrict__ q2h, const __nv_bfloat16* __restrict__ q2l,
    const __nv_bfloat16* __restrict__ k1h, const __nv_bfloat16* __restrict__ k1l,
    const __nv_bfloat16* __restrict__ k2h, const __nv_bfloat16* __restrict__ k2l,
    const __nv_bfloat16* __restrict__ vhh, const __nv_bfloat16* __restrict__ vhl,
    const float* __restrict__ lmb, float* __restrict__ y)
{
    extern __shared__ __align__(128) char smem[];
    const uint32_t sb = smem_to_u32(smem);
    const uint32_t sQ = sb, sKV = sb + 4 * FQ_TILE;
    const int tid = threadIdx.x;
    const int lane = tid & 31;
    const int w = tid >> 5;
    const int qt = blockIdx.x, h = blockIdx.y, b = blockIdx.z;
    const int bh = b * H_ + h;
    const size_t off = (size_t)bh * TQ_ * HD_;

    const __nv_bfloat16* kvsrc[6] = {
        k1h + off, k1l + off, k2h + off, k2l + off, vhh + off, vhl + off };
    const __nv_bfloat16* qsrc[4] = {
        q1h + off, q1l + off, q2h + off, q2l + off };

    // stage Q (4 tiles) + KV tile 0 (group 0); KV tile 1 (group 1)
    #pragma unroll
    for (int i = 0; i < 16; i++) {
        const int idx = tid + i * 256;          // 4096 chunks
        const int ts = idx >> 10;
        const int rem = idx & 1023;
        const int row = rem >> 3, c = rem & 7;
        cp_async16(sQ + ts * FQ_TILE + row * FSTR_B + c * 16,
                   qsrc[ts] + ((size_t)(qt * 128 + row)) * HD_ + c * 8);
    }
    flash_load_kv6(sKV, kvsrc, 0, tid);
    CP_COMMIT();
    flash_load_kv6(sKV + FKV_STAGE, kvsrc, 1, tid);
    CP_COMMIT();

    float o1[8][4], o2[8][4];
    float m1[2] = {-1e30f, -1e30f}, l1[2] = {0.f, 0.f};
    float m2[2] = {-1e30f, -1e30f}, l2[2] = {0.f, 0.f};
    #pragma unroll
    for (int j = 0; j < 8; j++)
        #pragma unroll
        for (int q = 0; q < 4; q++) { o1[j][q] = 0.f; o2[j][q] = 0.f; }

    CP_WAIT(1);
    __syncthreads();

    const uint32_t qrow = (w * 16 + (lane & 15)) * FSTR_B + (lane >> 4) * 16;
    const uint32_t lrow16 = (lane & 15) * FSTR_B + (lane >> 4) * 16;

    // Q1 fragments register-resident
    uint32_t q1hf[4][4], q1lf[4][4];
    #pragma unroll
    for (int kc = 0; kc < 4; kc++) {
        ldsm_x4(q1hf[kc][0], q1hf[kc][1], q1hf[kc][2], q1hf[kc][3],
                sQ + qrow + kc * 32);
        ldsm_x4(q1lf[kc][0], q1lf[kc][1], q1lf[kc][2], q1lf[kc][3],
                sQ + FQ_TILE + qrow + kc * 32);
    }

    for (int t = 0; t < 16; t++) {
        if (t > 0) {
            if (t + 1 < 16) { CP_WAIT(1); } else { CP_WAIT(0); }
            __syncthreads();
        }
        const uint32_t st = sKV + (t & 1) * FKV_STAGE;

        // ======== attention 1 ========
        {
            float s[8][4];
            #pragma unroll
            for (int j = 0; j < 8; j++)
                #pragma unroll
                for (int q = 0; q < 4; q++) s[j][q] = 0.f;

            #pragma unroll
            for (int kc = 0; kc < 4; kc++) {
                #pragma unroll
                for (int g = 0; g < 4; g++) {
                    const uint32_t addr = st + g * 16 * FSTR_B + lrow16 + kc * 32;
                    uint32_t h0, h1, h2, h3, l0, l1r, l2r, l3;
                    ldsm_x4(h0, h1, h2, h3, addr);
                    ldsm_x4(l0, l1r, l2r, l3, addr + FKV_TILE);
                    mma16816(s[2 * g],     q1hf[kc], h0, h2);
                    mma16816(s[2 * g],     q1hf[kc], l0, l2r);
                    mma16816(s[2 * g],     q1lf[kc], h0, h2);
                    mma16816(s[2 * g + 1], q1hf[kc], h1, h3);
                    mma16816(s[2 * g + 1], q1hf[kc], l1r, l3);
                    mma16816(s[2 * g + 1], q1lf[kc], h1, h3);
                }
            }
            softmax_step(s, m1, l1, o1);
            uint32_t ph[4][4], pl[4][4];
            build_p(s, ph, pl);
            pv_step(o1, ph, pl, st, lrow16);
        }

        // ======== attention 2 (Q2 frags re-ldsm'd) ========
        {
            float s[8][4];
            #pragma unroll
            for (int j = 0; j < 8; j++)
                #pragma unroll
                for (int q = 0; q < 4; q++) s[j][q] = 0.f;

            #pragma unroll
            for (int kc = 0; kc < 4; kc++) {
                uint32_t qh[4], ql[4];
                ldsm_x4(qh[0], qh[1], qh[2], qh[3], sQ + 2 * FQ_TILE + qrow + kc * 32);
                ldsm_x4(ql[0], ql[1], ql[2], ql[3], sQ + 3 * FQ_TILE + qrow + kc * 32);
                #pragma unroll
                for (int g = 0; g < 4; g++) {
                    const uint32_t addr = st + 2 * FKV_TILE + g * 16 * FSTR_B + lrow16 + kc * 32;
                    uint32_t h0, h1, h2, h3, l0, l1r, l2r, l3;
                    ldsm_x4(h0, h1, h2, h3, addr);
                    ldsm_x4(l0, l1r, l2r, l3, addr + FKV_TILE);
                    mma16816(s[2 * g],     qh, h0, h2);
                    mma16816(s[2 * g],     qh, l0, l2r);
                    mma16816(s[2 * g],     ql, h0, h2);
                    mma16816(s[2 * g + 1], qh, h1, h3);
                    mma16816(s[2 * g + 1], qh, l1r, l3);
                    mma16816(s[2 * g + 1], ql, h1, h3);
                }
            }
            softmax_step(s, m2, l2, o2);
            uint32_t ph[4][4], pl[4][4];
            build_p(s, ph, pl);
            pv_step(o2, ph, pl, st, lrow16);
        }

        __syncthreads();
        if (t + 2 < 16) {
            flash_load_kv6(st, kvsrc, t + 2, tid);
            CP_COMMIT();
        }
    }

    // epilogue
    const float cmul = log1pf(__expf(lmb[h]));
    const int r0 = lane >> 2, cb = (lane & 3) * 2;
    const float il10 = 1.f / l1[0], il11 = 1.f / l1[1];
    const float il20 = cmul / l2[0], il21 = cmul / l2[1];
    const size_t ybase = off + (size_t)(qt * 128 + w * 16) * HD_;
    #pragma unroll
    for (int j = 0; j < 8; j++) {
        float2 v0 = make_float2(o1[j][0] * il10 - o2[j][0] * il20,
                                o1[j][1] * il10 - o2[j][1] * il20);
        float2 v1 = make_float2(o1[j][2] * il11 - o2[j][2] * il21,
                                o1[j][3] * il11 - o2[j][3] * il21);
        *(float2*)&y[ybase + (size_t)r0 * HD_ + j * 8 + cb]       = v0;
        *(float2*)&y[ybase + (size_t)(r0 + 8) * HD_ + j * 8 + cb] = v1;
    }
}

// ===========================================================================
// GroupNorm stats
// ===========================================================================
__global__ void gn_stats_kernel(const float* __restrict__ y, float* __restrict__ stats)
{
    __shared__ float rs[256], rq[256];
    const int bh = blockIdx.x, tid = threadIdx.x;
    const float* p = y + (size_t)bh * TQ_ * HD_;
    float s = 0.f, q = 0.f;
    for (int i = tid * 4; i < TQ_ * HD_; i += 256 * 4) {
        float4 v = *(const float4*)(p + i);
        s += v.x + v.y + v.z + v.w;
        q += v.x * v.x + v.y * v.y + v.z * v.z + v.w * v.w;
    }
    rs[tid] = s; rq[tid] = q;
    __syncthreads();
    for (int o = 128; o; o >>= 1) {
        if (tid < o) { rs[tid] += rs[tid + o]; rq[tid] += rq[tid + o]; }
        __syncthreads();
    }
    if (tid == 0) {
        const float inv = 1.f / (float)(TQ_ * HD_);
        const float mu = rs[0] * inv;
        const float var = rq[0] * inv - mu * mu;
        stats[bh * 2 + 0] = mu;
        stats[bh * 2 + 1] = rsqrtf(var + EPS_);
    }
}

// ===========================================================================
// GroupNorm apply + transpose + bf16 hi/lo split
// ===========================================================================
__global__ void gn_apply_kernel(const float* __restrict__ y, const float* __restrict__ stats,
                                const float* __restrict__ gw, const float* __restrict__ gb,
                                __nv_bfloat16* __restrict__ hi, __nv_bfloat16* __restrict__ lo)
{
    const int i4 = blockIdx.x * blockDim.x + threadIdx.x;
    const int d4 = i4 & 255;
    const int t  = (i4 >> 8) & 1023;
    const int b  = i4 >> 18;
    const int c  = d4 * 4;
    const int h  = c >> 6;
    const int dd = c & 63;
    const float mu   = stats[(b * 16 + h) * 2 + 0];
    const float rstd = stats[(b * 16 + h) * 2 + 1];
    float4 v = *(const float4*)&y[(((size_t)(b * 16 + h)) * 1024 + t) * 64 + dd];
    float4 w = *(const float4*)&gw[c];
    float4 bb = *(const float4*)&gb[c];
    float f[4];
    f[0] = (v.x - mu) * rstd * w.x + bb.x;
    f[1] = (v.y - mu) * rstd * w.y + bb.y;
    f[2] = (v.z - mu) * rstd * w.z + bb.z;
    f[3] = (v.w - mu) * rstd * w.w + bb.w;
    __nv_bfloat16 hb[4], lb[4];
    #pragma unroll
    for (int j = 0; j < 4; j++) {
        hb[j] = __float2bfloat16_rn(f[j]);
        lb[j] = __float2bfloat16_rn(f[j] - __bfloat162float(hb[j]));
    }
    ((__nv_bfloat162*)hi)[2*i4 + 0] = __nv_bfloat162(hb[0], hb[1]);
    ((__nv_bfloat162*)hi)[2*i4 + 1] = __nv_bfloat162(hb[2], hb[3]);
    ((__nv_bfloat162*)lo)[2*i4 + 0] = __nv_bfloat162(lb[0], lb[1]);
    ((__nv_bfloat162*)lo)[2*i4 + 1] = __nv_bfloat162(lb[2], lb[3]);
}

// ===========================================================================
// Launch
// ===========================================================================
extern "C" void kernel_launch(void* const* d_in, const int* in_sizes, int n_in,
                              void* d_out, int out_size)
{
    const float* x_q  = (const float*)d_in[0];
    const float* x_kv = (const float*)d_in[1];
    const float* Wq   = (const float*)d_in[2];
    const float* Wkv  = (const float*)d_in[3];
    const float* Wc   = (const float*)d_in[4];
    const float* qn1  = (const float*)d_in[5];
    const float* kn1  = (const float*)d_in[6];
    const float* qn2  = (const float*)d_in[7];
    const float* kn2  = (const float*)d_in[8];
    const float* gn_w = (const float*)d_in[9];
    const float* gn_b = (const float*)d_in[10];
    const float* lmb  = (const float*)d_in[11];
    float* out = (float*)d_out;

    float *qproj, *kvproj, *y, *stats;
    cudaGetSymbolAddress((void**)&qproj,  g_qproj);
    cudaGetSymbolAddress((void**)&kvproj, g_kvproj);
    cudaGetSymbolAddress((void**)&y,      g_y);
    cudaGetSymbolAddress((void**)&stats,  g_stats);

    __nv_bfloat16 *xq_hi, *xq_lo, *xkv_hi, *xkv_lo;
    __nv_bfloat16 *wqt_hi, *wqt_lo, *wkvt_hi, *wkvt_lo, *wct_hi, *wct_lo;
    __nv_bfloat16 *ybt_hi, *ybt_lo;
    __nv_bfloat16 *q1h, *q1l, *q2h, *q2l, *k1h, *k1l, *k2h, *k2l, *vhh, *vhl;
    cudaGetSymbolAddress((void**)&xq_hi,   g_xq_hi);
    cudaGetSymbolAddress((void**)&xq_lo,   g_xq_lo);
    cudaGetSymbolAddress((void**)&xkv_hi,  g_xkv_hi);
    cudaGetSymbolAddress((void**)&xkv_lo,  g_xkv_lo);
    cudaGetSymbolAddress((void**)&wqt_hi,  g_wqt_hi);
    cudaGetSymbolAddress((void**)&wqt_lo,  g_wqt_lo);
    cudaGetSymbolAddress((void**)&wkvt_hi, g_wkvt_hi);
    cudaGetSymbolAddress((void**)&wkvt_lo, g_wkvt_lo);
    cudaGetSymbolAddress((void**)&wct_hi,  g_wct_hi);
    cudaGetSymbolAddress((void**)&wct_lo,  g_wct_lo);
    cudaGetSymbolAddress((void**)&ybt_hi,  g_ybt_hi);
    cudaGetSymbolAddress((void**)&ybt_lo,  g_ybt_lo);
    cudaGetSymbolAddress((void**)&q1h, g_q1h);
    cudaGetSymbolAddress((void**)&q1l, g_q1l);
    cudaGetSymbolAddress((void**)&q2h, g_q2h);
    cudaGetSymbolAddress((void**)&q2l, g_q2l);
    cudaGetSymbolAddress((void**)&k1h, g_k1h);
    cudaGetSymbolAddress((void**)&k1l, g_k1l);
    cudaGetSymbolAddress((void**)&k2h, g_k2h);
    cudaGetSymbolAddress((void**)&k2l, g_k2l);
    cudaGetSymbolAddress((void**)&vhh, g_vhh);
    cudaGetSymbolAddress((void**)&vhl, g_vhl);

    const int M = B_ * TQ_;  // 4096

    cudaFuncSetAttribute(gemm_mma, cudaFuncAttributeMaxDynamicSharedMemorySize, GM_SMEM);
    cudaFuncSetAttribute(flash_mma_kernel, cudaFuncAttributeMaxDynamicSharedMemorySize, FLASH_SMEM);

    // 0) split/convert operands to bf16 hi/lo
    {
        const int n4 = M * D_ / 4;
        split_kernel<<<n4 / 256, 256>>>(x_q,  xq_hi,  xq_lo,  n4);
        split_kernel<<<n4 / 256, 256>>>(x_kv, xkv_hi, xkv_lo, n4);
        split_transpose_kernel<<<dim3(2 * D_ / 32, D_ / 32), dim3(32, 8)>>>(Wq,  wqt_hi,  wqt_lo,  D_, 2 * D_);
        split_transpose_kernel<<<dim3(3 * D_ / 32, D_ / 32), dim3(32, 8)>>>(Wkv, wkvt_hi, wkvt_lo, D_, 3 * D_);
        split_transpose_kernel<<<dim3(D_ / 32, D_ / 32),     dim3(32, 8)>>>(Wc,  wct_hi,  wct_lo,  D_, D_);
    }

    // 1) projections (mma.sync bf16x3)
    gemm_mma<<<dim3(2 * D_ / 128, M / 128), 256, GM_SMEM>>>(xq_hi,  xq_lo,  wqt_hi,  wqt_lo,  qproj,  M, 2 * D_, D_);
    gemm_mma<<<dim3(3 * D_ / 128, M / 128), 256, GM_SMEM>>>(xkv_hi, xkv_lo, wkvt_hi, wkvt_lo, kvproj, M, 3 * D_, D_);

    // 2) RMSNorm + head reshape + bf16 hi/lo split
    rms_q_kernel<<<M * H_ * 2 * 32 / 256, 256>>>(qproj, qn1, qn2, q1h, q1l, q2h, q2l);
    rms_kv_kernel<<<M * H_ * 3 * 32 / 256, 256>>>(kvproj, kn1, kn2, k1h, k1l, k2h, k2l, vhh, vhl);

    // 3) merged dual flash attention (mma.sync bf16x3, single kv pass)
    flash_mma_kernel<<<dim3(TQ_ / 128, H_, B_), 256, FLASH_SMEM>>>(
        q1h, q1l, q2h, q2l, k1h, k1l, k2h, k2l, vhh, vhl, lmb, y);

    // 4) GroupNorm
    gn_stats_kernel<<<B_ * H_, 256>>>(y, stats);
    gn_apply_kernel<<<(B_ * TQ_ * D_ / 4) / 256, 256>>>(y, stats, gn_w, gn_b, ybt_hi, ybt_lo);

    // 5) output projection (mma.sync bf16x3)
    gemm_mma<<<dim3(D_ / 128, M / 128), 256, GM_SMEM>>>(ybt_hi, ybt_lo, wct_hi, wct_lo, out, M, D_, D_);
}

// round 9
// speedup vs baseline: 2.3908x; 1.0240x over previous
#include <cuda_runtime.h>
#include <cuda_bf16.h>
#include <math.h>
#include <stdint.h>

// Problem constants
#define B_    4
#define TQ_   1024
#define TKV_  1024
#define D_    1024
#define H_    16
#define HD_   64
#define EPS_  1e-5f

// ===========================================================================
// PTX helpers (baseline features only — compute_103 virtual arch safe)
// ===========================================================================
__device__ __forceinline__ uint32_t smem_to_u32(const void* smem_ptr) {
    uint32_t addr;
    asm("{ .reg .u64 tmp; cvta.to.shared.u64 tmp, %1; cvt.u32.u64 %0, tmp; }"
        : "=r"(addr) : "l"(smem_ptr));
    return addr;
}

__device__ __forceinline__ void cp_async16(uint32_t dst, const void* src) {
    asm volatile("cp.async.cg.shared.global [%0], [%1], 16;" :: "r"(dst), "l"(src));
}
#define CP_COMMIT() asm volatile("cp.async.commit_group;" ::: "memory")
#define CP_WAIT(n)  asm volatile("cp.async.wait_group %0;" :: "n"(n) : "memory")

__device__ __forceinline__ void ldsm_x4(uint32_t& r0, uint32_t& r1, uint32_t& r2,
                                        uint32_t& r3, uint32_t addr) {
    asm volatile("ldmatrix.sync.aligned.m8n8.x4.shared.b16 {%0,%1,%2,%3}, [%4];"
        : "=r"(r0), "=r"(r1), "=r"(r2), "=r"(r3) : "r"(addr));
}

__device__ __forceinline__ void ldsm_x4_t(uint32_t& r0, uint32_t& r1, uint32_t& r2,
                                          uint32_t& r3, uint32_t addr) {
    asm volatile("ldmatrix.sync.aligned.m8n8.x4.trans.shared.b16 {%0,%1,%2,%3}, [%4];"
        : "=r"(r0), "=r"(r1), "=r"(r2), "=r"(r3) : "r"(addr));
}

// D += A * B  (m16n8k16, bf16 inputs, fp32 accum)
__device__ __forceinline__ void mma16816(float* d, const uint32_t* a,
                                         uint32_t b0, uint32_t b1) {
    asm volatile(
        "mma.sync.aligned.m16n8k16.row.col.f32.bf16.bf16.f32 "
        "{%0,%1,%2,%3}, {%4,%5,%6,%7}, {%8,%9}, {%0,%1,%2,%3};"
        : "+f"(d[0]), "+f"(d[1]), "+f"(d[2]), "+f"(d[3])
        : "r"(a[0]), "r"(a[1]), "r"(a[2]), "r"(a[3]), "r"(b0), "r"(b1));
}

__device__ __forceinline__ uint32_t pack_bf16(float a, float b) {
    __nv_bfloat162 t = __floats2bfloat162_rn(a, b);
    return *reinterpret_cast<uint32_t*>(&t);
}

// ===========================================================================
// Device scratch
// ===========================================================================
__device__ float g_y     [B_ * H_ * TQ_  * HD_];
__device__ float g_stats [B_ * H_ * 2];

__device__ __nv_bfloat16 g_xq_hi [B_ * TQ_ * D_];
__device__ __nv_bfloat16 g_xq_lo [B_ * TQ_ * D_];
__device__ __nv_bfloat16 g_xkv_hi[B_ * TKV_ * D_];
__device__ __nv_bfloat16 g_xkv_lo[B_ * TKV_ * D_];
__device__ __nv_bfloat16 g_wqt_hi [2 * D_ * D_];
__device__ __nv_bfloat16 g_wqt_lo [2 * D_ * D_];
__device__ __nv_bfloat16 g_wkvt_hi[3 * D_ * D_];
__device__ __nv_bfloat16 g_wkvt_lo[3 * D_ * D_];
__device__ __nv_bfloat16 g_wct_hi [D_ * D_];
__device__ __nv_bfloat16 g_wct_lo [D_ * D_];
__device__ __nv_bfloat16 g_ybt_hi [B_ * TQ_ * D_];
__device__ __nv_bfloat16 g_ybt_lo [B_ * TQ_ * D_];

// bf16 hi/lo attention operands, (B,H,T,HD)
__device__ __nv_bfloat16 g_q1h[B_ * H_ * TQ_ * HD_];
__device__ __nv_bfloat16 g_q1l[B_ * H_ * TQ_ * HD_];
__device__ __nv_bfloat16 g_q2h[B_ * H_ * TQ_ * HD_];
__device__ __nv_bfloat16 g_q2l[B_ * H_ * TQ_ * HD_];
__device__ __nv_bfloat16 g_k1h[B_ * H_ * TKV_ * HD_];
__device__ __nv_bfloat16 g_k1l[B_ * H_ * TKV_ * HD_];
__device__ __nv_bfloat16 g_k2h[B_ * H_ * TKV_ * HD_];
__device__ __nv_bfloat16 g_k2l[B_ * H_ * TKV_ * HD_];
__device__ __nv_bfloat16 g_vhh[B_ * H_ * TKV_ * HD_];
__device__ __nv_bfloat16 g_vhl[B_ * H_ * TKV_ * HD_];

// ===========================================================================
// Split fp32 -> bf16 hi/lo
// ===========================================================================
__global__ void split_kernel(const float* __restrict__ x,
                             __nv_bfloat16* __restrict__ hi,
                             __nv_bfloat16* __restrict__ lo, int n4)
{
    const int i = blockIdx.x * blockDim.x + threadIdx.x;
    if (i >= n4) return;
    float4 v = ((const float4*)x)[i];
    float f[4] = {v.x, v.y, v.z, v.w};
    __nv_bfloat16 h[4], l[4];
    #pragma unroll
    for (int j = 0; j < 4; j++) {
        h[j] = __float2bfloat16_rn(f[j]);
        l[j] = __float2bfloat16_rn(f[j] - __bfloat162float(h[j]));
    }
    ((__nv_bfloat162*)hi)[2*i + 0] = __nv_bfloat162(h[0], h[1]);
    ((__nv_bfloat162*)hi)[2*i + 1] = __nv_bfloat162(h[2], h[3]);
    ((__nv_bfloat162*)lo)[2*i + 0] = __nv_bfloat162(l[0], l[1]);
    ((__nv_bfloat162*)lo)[2*i + 1] = __nv_bfloat162(l[2], l[3]);
}

// ===========================================================================
// Transpose + split: W [K,N] fp32 -> Wt_hi/lo [N,K] bf16 (K-major)
// ===========================================================================
__global__ void split_transpose_kernel(const float* __restrict__ W,
                                       __nv_bfloat16* __restrict__ hi,
                                       __nv_bfloat16* __restrict__ lo, int K, int N)
{
    __shared__ float t[32][33];
    const int n0 = blockIdx.x * 32, k0 = blockIdx.y * 32;
    #pragma unroll
    for (int dy = 0; dy < 32; dy += 8)
        t[threadIdx.y + dy][threadIdx.x] =
            W[(size_t)(k0 + threadIdx.y + dy) * N + n0 + threadIdx.x];
    __syncthreads();
    #pragma unroll
    for (int dy = 0; dy < 32; dy += 8) {
        const int n = n0 + threadIdx.y + dy, k = k0 + threadIdx.x;
        const float v = t[threadIdx.x][threadIdx.y + dy];
        const __nv_bfloat16 h = __float2bfloat16_rn(v);
        hi[(size_t)n * K + k] = h;
        lo[(size_t)n * K + k] = __float2bfloat16_rn(v - __bfloat162float(h));
    }
}

// ===========================================================================
// mma.sync bf16x3 GEMM shared pieces
// ===========================================================================
#define SAST       40
#define GM_TILE_B  (128 * SAST * 2)
#define GM_STAGE_B (4 * GM_TILE_B)
#define GM_SMEM    (2 * GM_STAGE_B)       // 81920; epilogue reuse needs 67584

__device__ __forceinline__ void gm_load_stage(
    uint32_t stage_base, const __nv_bfloat16* const* srcs, int k0, int K, int tid)
{
    #pragma unroll
    for (int t = 0; t < 4; t++) {
        const __nv_bfloat16* s = srcs[t] + k0;
        const uint32_t tb = stage_base + t * GM_TILE_B;
        #pragma unroll
        for (int i = 0; i < 2; i++) {
            const int idx = tid + i * 256;
            const int row = idx >> 2, c16 = idx & 3;
            cp_async16(tb + row * (SAST * 2) + c16 * 16,
                       s + (size_t)row * K + c16 * 8);
        }
    }
    CP_COMMIT();
}

// mainloop producing acc[4][4][4]; factored as macro-like inline
__device__ __forceinline__ void gm_mainloop(
    uint32_t sb, const __nv_bfloat16* const* srcs, int K,
    int tid, int lane, int wm, int wn, float acc[4][4][4])
{
    const int nch = K >> 5;
    gm_load_stage(sb, srcs, 0, K, tid);

    const uint32_t lrow = (lane & 15);
    const uint32_t lcol16 = (lane >> 4) * 16;

    for (int c = 0; c < nch; c++) {
        if (c + 1 < nch) gm_load_stage(sb + ((c + 1) & 1) * GM_STAGE_B, srcs, (c + 1) << 5, K, tid);
        if (c + 1 < nch) { CP_WAIT(1); } else { CP_WAIT(0); }
        __syncthreads();

        const uint32_t st = sb + (c & 1) * GM_STAGE_B;
        #pragma unroll
        for (int ks = 0; ks < 2; ks++) {
            const uint32_t coff = lcol16 + ks * 32;
            uint32_t bh[2][4], bl[2][4];
            #pragma unroll
            for (int nt = 0; nt < 2; nt++) {
                const uint32_t baddr = st + 2 * GM_TILE_B
                    + (wn * 32 + nt * 16 + lrow) * (SAST * 2) + coff;
                ldsm_x4(bh[nt][0], bh[nt][1], bh[nt][2], bh[nt][3], baddr);
                ldsm_x4(bl[nt][0], bl[nt][1], bl[nt][2], bl[nt][3], baddr + GM_TILE_B);
            }
            #pragma unroll
            for (int mt = 0; mt < 4; mt++) {
                const uint32_t aaddr = st
                    + (wm * 64 + mt * 16 + lrow) * (SAST * 2) + coff;
                uint32_t ah[4], al[4];
                ldsm_x4(ah[0], ah[1], ah[2], ah[3], aaddr);
                ldsm_x4(al[0], al[1], al[2], al[3], aaddr + GM_TILE_B);
                #pragma unroll
                for (int nt = 0; nt < 2; nt++) {
                    #pragma unroll
                    for (int hh = 0; hh < 2; hh++) {
                        float* d = acc[mt][nt * 2 + hh];
                        uint32_t bfh0 = bh[nt][hh], bfh1 = bh[nt][hh + 2];
                        mma16816(d, ah, bfh0, bfh1);
                        mma16816(d, ah, bl[nt][hh], bl[nt][hh + 2]);
                        mma16816(d, al, bfh0, bfh1);
                    }
                }
            }
        }
        __syncthreads();
    }
}

// ===========================================================================
// Plain GEMM (fp32 C output) — used for the final out-projection
// ===========================================================================
__global__ __launch_bounds__(256) void gemm_mma(
    const __nv_bfloat16* __restrict__ Ahi, const __nv_bfloat16* __restrict__ Alo,
    const __nv_bfloat16* __restrict__ Bhi, const __nv_bfloat16* __restrict__ Blo,
    float* __restrict__ C, int M, int N, int K)
{
    extern __shared__ __align__(128) char smem[];
    const uint32_t sb = smem_to_u32(smem);
    const int tid = threadIdx.x;
    const int lane = tid & 31;
    const int wid = tid >> 5;
    const int wm = wid & 1;
    const int wn = wid >> 1;
    const int bx = blockIdx.x, by = blockIdx.y;

    const __nv_bfloat16* srcs[4] = {
        Ahi + (size_t)(by * 128) * K, Alo + (size_t)(by * 128) * K,
        Bhi + (size_t)(bx * 128) * K, Blo + (size_t)(bx * 128) * K };

    float acc[4][4][4];
    #pragma unroll
    for (int a = 0; a < 4; a++)
        #pragma unroll
        for (int b = 0; b < 4; b++)
            #pragma unroll
            for (int c = 0; c < 4; c++) acc[a][b][c] = 0.f;

    gm_mainloop(sb, srcs, K, tid, lane, wm, wn, acc);

    #pragma unroll
    for (int mt = 0; mt < 4; mt++) {
        const int row0 = by * 128 + wm * 64 + mt * 16 + (lane >> 2);
        #pragma unroll
        for (int n8 = 0; n8 < 4; n8++) {
            const int col = bx * 128 + wn * 32 + n8 * 8 + (lane & 3) * 2;
            float2 o0 = make_float2(acc[mt][n8][0], acc[mt][n8][1]);
            float2 o1 = make_float2(acc[mt][n8][2], acc[mt][n8][3]);
            *(float2*)&C[(size_t)row0 * N + col]       = o0;
            *(float2*)&C[(size_t)(row0 + 8) * N + col] = o1;
        }
    }
}

// ===========================================================================
// Projection GEMM with fused RMSNorm + head-reshape + bf16 hi/lo split.
// Output heads (64 cols) are aligned within the 128-col tile: which = cg>>10
// selects the destination tensor triple; which<2 gets RMS (×norm weight
// ×qscale), which==2 (V) is a plain copy. Dst layout: (B,H,T,HD) bf16.
// ===========================================================================
struct RmsDst {
    const float* w0;            // norm weight for which==0
    const float* w1;            // norm weight for which==1
    __nv_bfloat16 *h0, *l0;     // dst hi/lo for which==0
    __nv_bfloat16 *h1, *l1;     // which==1
    __nv_bfloat16 *h2, *l2;     // which==2 (V; may be null for q-GEMM)
    float qscale;               // 0.125 for q, 1.0 for kv
};

__global__ __launch_bounds__(256) void gemm_mma_rms(
    const __nv_bfloat16* __restrict__ Ahi, const __nv_bfloat16* __restrict__ Alo,
    const __nv_bfloat16* __restrict__ Bhi, const __nv_bfloat16* __restrict__ Blo,
    RmsDst P, int M, int N, int K)
{
    extern __shared__ __align__(128) char smem[];
    const uint32_t sb = smem_to_u32(smem);
    const int tid = threadIdx.x;
    const int lane = tid & 31;
    const int wid = tid >> 5;
    const int wm = wid & 1;
    const int wn = wid >> 1;
    const int bx = blockIdx.x, by = blockIdx.y;

    const __nv_bfloat16* srcs[4] = {
        Ahi + (size_t)(by * 128) * K, Alo + (size_t)(by * 128) * K,
        Bhi + (size_t)(bx * 128) * K, Blo + (size_t)(bx * 128) * K };

    float acc[4][4][4];
    #pragma unroll
    for (int a = 0; a < 4; a++)
        #pragma unroll
        for (int b = 0; b < 4; b++)
            #pragma unroll
            for (int c = 0; c < 4; c++) acc[a][b][c] = 0.f;

    gm_mainloop(sb, srcs, K, tid, lane, wm, wn, acc);

    // ---- epilogue: acc -> smem fp32 tile [128][132] ----
    float* sE = (float*)smem;
    #pragma unroll
    for (int mt = 0; mt < 4; mt++) {
        const int r0 = wm * 64 + mt * 16 + (lane >> 2);
        #pragma unroll
        for (int n8 = 0; n8 < 4; n8++) {
            const int c = wn * 32 + n8 * 8 + (lane & 3) * 2;
            *(float2*)&sE[r0 * 132 + c]       = make_float2(acc[mt][n8][0], acc[mt][n8][1]);
            *(float2*)&sE[(r0 + 8) * 132 + c] = make_float2(acc[mt][n8][2], acc[mt][n8][3]);
        }
    }
    __syncthreads();

    // ---- per-row RMS over each 64-col head half, split, store ----
    const int bq    = by >> 3;                 // batch (128*by + r) >> 10
    const int hloc  = lane >> 4;               // 0/1: which head half of the tile
    const int cg    = bx * 128 + hloc * 64;    // global col of head base
    const int which = cg >> 10;
    const int hh    = (cg >> 6) & 15;
    const int d0    = (lane & 15) * 4;
    const bool donorm = (which < 2);
    const float* wptr = (which == 0) ? P.w0 : P.w1;
    float4 wv = make_float4(1.f, 1.f, 1.f, 1.f);
    if (donorm) wv = *(const float4*)&wptr[d0];
    __nv_bfloat16* dh = (which == 0) ? P.h0 : ((which == 1) ? P.h1 : P.h2);
    __nv_bfloat16* dl = (which == 0) ? P.l0 : ((which == 1) ? P.l1 : P.l2);
    const int w8 = wid * 16;

    #pragma unroll 4
    for (int i = 0; i < 16; i++) {
        const int r = w8 + i;
        float4 v = *(const float4*)&sE[r * 132 + lane * 4];
        float ss = v.x * v.x + v.y * v.y + v.z * v.z + v.w * v.w;
        ss += __shfl_xor_sync(0xffffffffu, ss, 1);
        ss += __shfl_xor_sync(0xffffffffu, ss, 2);
        ss += __shfl_xor_sync(0xffffffffu, ss, 4);
        ss += __shfl_xor_sync(0xffffffffu, ss, 8);
        const float rr = donorm ? rsqrtf(ss * (1.0f / 64.0f) + EPS_) * P.qscale : 1.f;
        const float f0 = v.x * rr * wv.x;
        const float f1 = v.y * rr * wv.y;
        const float f2 = v.z * rr * wv.z;
        const float f3 = v.w * rr * wv.w;
        const __nv_bfloat16 b0 = __float2bfloat16_rn(f0);
        const __nv_bfloat16 b1 = __float2bfloat16_rn(f1);
        const __nv_bfloat16 b2 = __float2bfloat16_rn(f2);
        const __nv_bfloat16 b3 = __float2bfloat16_rn(f3);
        const uint32_t H01 = pack_bf16(__bfloat162float(b0), 0.f) |
                             (pack_bf16(__bfloat162float(b1), 0.f) << 16);
        const uint32_t H23 = pack_bf16(__bfloat162float(b2), 0.f) |
                             (pack_bf16(__bfloat162float(b3), 0.f) << 16);
        const uint32_t L01 = pack_bf16(f0 - __bfloat162float(b0), f1 - __bfloat162float(b1));
        const uint32_t L23 = pack_bf16(f2 - __bfloat162float(b2), f3 - __bfloat162float(b3));
        const int t = (by & 7) * 128 + r;
        const size_t idx = ((((size_t)bq * 16 + hh) * 1024) + t) * 64 + d0;
        *(uint2*)&dh[idx] = make_uint2(H01, H23);
        *(uint2*)&dl[idx] = make_uint2(L01, L23);
    }
}

// ===========================================================================
// MERGED dual flash attention with mma.sync bf16x3 (unchanged from R8 pass)
// ===========================================================================
#define FSTR_B    144
#define FQ_TILE   (128 * FSTR_B)
#define FKV_TILE  (64 * FSTR_B)
#define FKV_STAGE (6 * FKV_TILE)
#define FLASH_SMEM (4 * FQ_TILE + 2 * FKV_STAGE)   // 184320

__device__ __forceinline__ void flash_load_kv6(
    uint32_t dst, const __nv_bfloat16* const* srcs, int kt, int tid)
{
    #pragma unroll
    for (int i = 0; i < 12; i++) {
        const int idx = tid + i * 256;
        const int t = idx >> 9;
        const int rem = idx & 511;
        const int row = rem >> 3, c = rem & 7;
        cp_async16(dst + t * FKV_TILE + row * FSTR_B + c * 16,
                   srcs[t] + ((size_t)(kt * 64 + row)) * HD_ + c * 8);
    }
}

__device__ __forceinline__ void softmax_step(float s[8][4], float m[2], float l[2],
                                             float o[8][4])
{
    float mx0 = -1e30f, mx1 = -1e30f;
    #pragma unroll
    for (int j = 0; j < 8; j++) {
        mx0 = fmaxf(mx0, fmaxf(s[j][0], s[j][1]));
        mx1 = fmaxf(mx1, fmaxf(s[j][2], s[j][3]));
    }
    mx0 = fmaxf(mx0, __shfl_xor_sync(0xffffffffu, mx0, 1));
    mx0 = fmaxf(mx0, __shfl_xor_sync(0xffffffffu, mx0, 2));
    mx1 = fmaxf(mx1, __shfl_xor_sync(0xffffffffu, mx1, 1));
    mx1 = fmaxf(mx1, __shfl_xor_sync(0xffffffffu, mx1, 2));
    const float mn0 = fmaxf(m[0], mx0), mn1 = fmaxf(m[1], mx1);
    const float a0 = __expf(m[0] - mn0), a1 = __expf(m[1] - mn1);
    m[0] = mn0; m[1] = mn1;
    float ps0 = 0.f, ps1 = 0.f;
    #pragma unroll
    for (int j = 0; j < 8; j++) {
        s[j][0] = __expf(s[j][0] - mn0);
        s[j][1] = __expf(s[j][1] - mn0);
        s[j][2] = __expf(s[j][2] - mn1);
        s[j][3] = __expf(s[j][3] - mn1);
        ps0 += s[j][0] + s[j][1];
        ps1 += s[j][2] + s[j][3];
    }
    ps0 += __shfl_xor_sync(0xffffffffu, ps0, 1);
    ps0 += __shfl_xor_sync(0xffffffffu, ps0, 2);
    ps1 += __shfl_xor_sync(0xffffffffu, ps1, 1);
    ps1 += __shfl_xor_sync(0xffffffffu, ps1, 2);
    l[0] = l[0] * a0 + ps0;
    l[1] = l[1] * a1 + ps1;
    #pragma unroll
    for (int j = 0; j < 8; j++) {
        o[j][0] *= a0; o[j][1] *= a0;
        o[j][2] *= a1; o[j][3] *= a1;
    }
}

__device__ __forceinline__ void build_p(const float s[8][4],
                                        uint32_t ph[4][4], uint32_t pl[4][4])
{
    #pragma unroll
    for (int kc = 0; kc < 4; kc++) {
        const int j0 = 2 * kc, j1 = 2 * kc + 1;
        ph[kc][0] = pack_bf16(s[j0][0], s[j0][1]);
        ph[kc][1] = pack_bf16(s[j0][2], s[j0][3]);
        ph[kc][2] = pack_bf16(s[j1][0], s[j1][1]);
        ph[kc][3] = pack_bf16(s[j1][2], s[j1][3]);
        float r00 = s[j0][0] - __bfloat162float(__float2bfloat16_rn(s[j0][0]));
        float r01 = s[j0][1] - __bfloat162float(__float2bfloat16_rn(s[j0][1]));
        float r02 = s[j0][2] - __bfloat162float(__float2bfloat16_rn(s[j0][2]));
        float r03 = s[j0][3] - __bfloat162float(__float2bfloat16_rn(s[j0][3]));
        float r10 = s[j1][0] - __bfloat162float(__float2bfloat16_rn(s[j1][0]));
        float r11 = s[j1][1] - __bfloat162float(__float2bfloat16_rn(s[j1][1]));
        float r12 = s[j1][2] - __bfloat162float(__float2bfloat16_rn(s[j1][2]));
        float r13 = s[j1][3] - __bfloat162float(__float2bfloat16_rn(s[j1][3]));
        pl[kc][0] = pack_bf16(r00, r01);
        pl[kc][1] = pack_bf16(r02, r03);
        pl[kc][2] = pack_bf16(r10, r11);
        pl[kc][3] = pack_bf16(r12, r13);
    }
}

__device__ __forceinline__ void pv_step(float o[8][4], const uint32_t ph[4][4],
                                        const uint32_t pl[4][4], uint32_t st,
                                        uint32_t lrow16)
{
    #pragma unroll
    for (int kc = 0; kc < 4; kc++) {
        #pragma unroll
        for (int hg = 0; hg < 4; hg++) {
            const uint32_t addr = st + kc * 16 * FSTR_B + lrow16 + hg * 32;
            uint32_t vh0, vh1, vh2, vh3, vl0, vl1, vl2, vl3;
            ldsm_x4_t(vh0, vh1, vh2, vh3, addr + 4 * FKV_TILE);
            ldsm_x4_t(vl0, vl1, vl2, vl3, addr + 5 * FKV_TILE);
            mma16816(o[2 * hg],     ph[kc], vh0, vh1);
            mma16816(o[2 * hg],     pl[kc], vh0, vh1);
            mma16816(o[2 * hg],     ph[kc], vl0, vl1);
            mma16816(o[2 * hg + 1], ph[kc], vh2, vh3);
            mma16816(o[2 * hg + 1], pl[kc], vh2, vh3);
            mma16816(o[2 * hg + 1], ph[kc], vl2, vl3);
        }
    }
}

__global__ __launch_bounds__(256, 1) void flash_mma_kernel(
    const __nv_bfloat16* __restrict__ q1h, const __nv_bfloat16* __restrict__ q1l,
    const __nv_bfloat16* __restrict__ q2h, const __nv_bfloat16* __restrict__ q2l,
    const __nv_bfloat16* __restrict__ k1h, const __nv_bfloat16* __restrict__ k1l,
    const __nv_bfloat16* __restrict__ k2h, const __nv_bfloat16* __restrict__ k2l,
    const __nv_bfloat16* __restrict__ vhh, const __nv_bfloat16* __restrict__ vhl,
    const float* __restrict__ lmb, float* __restrict__ y)
{
    extern __shared__ __align__(128) char smem[];
    const uint32_t sb = smem_to_u32(smem);
    const uint32_t sQ = sb, sKV = sb + 4 * FQ_TILE;
    const int tid = threadIdx.x;
    const int lane = tid & 31;
    const int w = tid >> 5;
    const int qt = blockIdx.x, h = blockIdx.y, b = blockIdx.z;
    const int bh = b * H_ + h;
    const size_t off = (size_t)bh * TQ_ * HD_;

    const __nv_bfloat16* kvsrc[6] = {
        k1h + off, k1l + off, k2h + off, k2l + off, vhh + off, vhl + off };
    const __nv_bfloat16* qsrc[4] = {
        q1h + off, q1l + off, q2h + off, q2l + off };

    #pragma unroll
    for (int i = 0; i < 16; i++) {
        const int idx = tid + i * 256;
        const int ts = idx >> 10;
        const int rem = idx & 1023;
        const int row = rem >> 3, c = rem & 7;
        cp_async16(sQ + ts * FQ_TILE + row * FSTR_B + c * 16,
                   qsrc[ts] + ((size_t)(qt * 128 + row)) * HD_ + c * 8);
    }
    flash_load_kv6(sKV, kvsrc, 0, tid);
    CP_COMMIT();
    flash_load_kv6(sKV + FKV_STAGE, kvsrc, 1, tid);
    CP_COMMIT();

    float o1[8][4], o2[8][4];
    float m1[2] = {-1e30f, -1e30f}, l1[2] = {0.f, 0.f};
    float m2[2] = {-1e30f, -1e30f}, l2[2] = {0.f, 0.f};
    #pragma unroll
    for (int j = 0; j < 8; j++)
        #pragma unroll
        for (int q = 0; q < 4; q++) { o1[j][q] = 0.f; o2[j][q] = 0.f; }

    CP_WAIT(1);
    __syncthreads();

    const uint32_t qrow = (w * 16 + (lane & 15)) * FSTR_B + (lane >> 4) * 16;
    const uint32_t lrow16 = (lane & 15) * FSTR_B + (lane >> 4) * 16;

    uint32_t q1hf[4][4], q1lf[4][4];
    #pragma unroll
    for (int kc = 0; kc < 4; kc++) {
        ldsm_x4(q1hf[kc][0], q1hf[kc][1], q1hf[kc][2], q1hf[kc][3],
                sQ + qrow + kc * 32);
        ldsm_x4(q1lf[kc][0], q1lf[kc][1], q1lf[kc][2], q1lf[kc][3],
                sQ + FQ_TILE + qrow + kc * 32);
    }

    for (int t = 0; t < 16; t++) {
        if (t > 0) {
            if (t + 1 < 16) { CP_WAIT(1); } else { CP_WAIT(0); }
            __syncthreads();
        }
        const uint32_t st = sKV + (t & 1) * FKV_STAGE;

        // ======== attention 1 ========
        {
            float s[8][4];
            #pragma unroll
            for (int j = 0; j < 8; j++)
                #pragma unroll
                for (int q = 0; q < 4; q++) s[j][q] = 0.f;

            #pragma unroll
            for (int kc = 0; kc < 4; kc++) {
                #pragma unroll
                for (int g = 0; g < 4; g++) {
                    const uint32_t addr = st + g * 16 * FSTR_B + lrow16 + kc * 32;
                    uint32_t h0, h1, h2, h3, l0, l1r, l2r, l3;
                    ldsm_x4(h0, h1, h2, h3, addr);
                    ldsm_x4(l0, l1r, l2r, l3, addr + FKV_TILE);
                    mma16816(s[2 * g],     q1hf[kc], h0, h2);
                    mma16816(s[2 * g],     q1hf[kc], l0, l2r);
                    mma16816(s[2 * g],     q1lf[kc], h0, h2);
                    mma16816(s[2 * g + 1], q1hf[kc], h1, h3);
                    mma16816(s[2 * g + 1], q1hf[kc], l1r, l3);
                    mma16816(s[2 * g + 1], q1lf[kc], h1, h3);
                }
            }
            softmax_step(s, m1, l1, o1);
            uint32_t ph[4][4], pl[4][4];
            build_p(s, ph, pl);
            pv_step(o1, ph, pl, st, lrow16);
        }

        // ======== attention 2 (Q2 frags re-ldsm'd) ========
        {
            float s[8][4];
            #pragma unroll
            for (int j = 0; j < 8; j++)
                #pragma unroll
                for (int q = 0; q < 4; q++) s[j][q] = 0.f;

            #pragma unroll
            for (int kc = 0; kc < 4; kc++) {
                uint32_t qh[4], ql[4];
                ldsm_x4(qh[0], qh[1], qh[2], qh[3], sQ + 2 * FQ_TILE + qrow + kc * 32);
                ldsm_x4(ql[0], ql[1], ql[2], ql[3], sQ + 3 * FQ_TILE + qrow + kc * 32);
                #pragma unroll
                for (int g = 0; g < 4; g++) {
                    const uint32_t addr = st + 2 * FKV_TILE + g * 16 * FSTR_B + lrow16 + kc * 32;
                    uint32_t h0, h1, h2, h3, l0, l1r, l2r, l3;
                    ldsm_x4(h0, h1, h2, h3, addr);
                    ldsm_x4(l0, l1r, l2r, l3, addr + FKV_TILE);
                    mma16816(s[2 * g],     qh, h0, h2);
                    mma16816(s[2 * g],     qh, l0, l2r);
                    mma16816(s[2 * g],     ql, h0, h2);
                    mma16816(s[2 * g + 1], qh, h1, h3);
                    mma16816(s[2 * g + 1], qh, l1r, l3);
                    mma16816(s[2 * g + 1], ql, h1, h3);
                }
            }
            softmax_step(s, m2, l2, o2);
            uint32_t ph[4][4], pl[4][4];
            build_p(s, ph, pl);
            pv_step(o2, ph, pl, st, lrow16);
        }

        __syncthreads();
        if (t + 2 < 16) {
            flash_load_kv6(st, kvsrc, t + 2, tid);
            CP_COMMIT();
        }
    }

    // epilogue
    const float cmul = log1pf(__expf(lmb[h]));
    const int r0 = lane >> 2, cb = (lane & 3) * 2;
    const float il10 = 1.f / l1[0], il11 = 1.f / l1[1];
    const float il20 = cmul / l2[0], il21 = cmul / l2[1];
    const size_t ybase = off + (size_t)(qt * 128 + w * 16) * HD_;
    #pragma unroll
    for (int j = 0; j < 8; j++) {
        float2 v0 = make_float2(o1[j][0] * il10 - o2[j][0] * il20,
                                o1[j][1] * il10 - o2[j][1] * il20);
        float2 v1 = make_float2(o1[j][2] * il11 - o2[j][2] * il21,
                                o1[j][3] * il11 - o2[j][3] * il21);
        *(float2*)&y[ybase + (size_t)r0 * HD_ + j * 8 + cb]       = v0;
        *(float2*)&y[ybase + (size_t)(r0 + 8) * HD_ + j * 8 + cb] = v1;
    }
}

// ===========================================================================
// GroupNorm stats
// ===========================================================================
__global__ void gn_stats_kernel(const float* __restrict__ y, float* __restrict__ stats)
{
    __shared__ float rs[256], rq[256];
    const int bh = blockIdx.x, tid = threadIdx.x;
    const float* p = y + (size_t)bh * TQ_ * HD_;
    float s = 0.f, q = 0.f;
    for (int i = tid * 4; i < TQ_ * HD_; i += 256 * 4) {
        float4 v = *(const float4*)(p + i);
        s += v.x + v.y + v.z + v.w;
        q += v.x * v.x + v.y * v.y + v.z * v.z + v.w * v.w;
    }
    rs[tid] = s; rq[tid] = q;
    __syncthreads();
    for (int o = 128; o; o >>= 1) {
        if (tid < o) { rs[tid] += rs[tid + o]; rq[tid] += rq[tid + o]; }
        __syncthreads();
    }
    if (tid == 0) {
        const float inv = 1.f / (float)(TQ_ * HD_);
        const float mu = rs[0] * inv;
        const float var = rq[0] * inv - mu * mu;
        stats[bh * 2 + 0] = mu;
        stats[bh * 2 + 1] = rsqrtf(var + EPS_);
    }
}

// ===========================================================================
// GroupNorm apply + transpose + bf16 hi/lo split
// ===========================================================================
__global__ void gn_apply_kernel(const float* __restrict__ y, const float* __restrict__ stats,
                                const float* __restrict__ gw, const float* __restrict__ gb,
                                __nv_bfloat16* __restrict__ hi, __nv_bfloat16* __restrict__ lo)
{
    const int i4 = blockIdx.x * blockDim.x + threadIdx.x;
    const int d4 = i4 & 255;
    const int t  = (i4 >> 8) & 1023;
    const int b  = i4 >> 18;
    const int c  = d4 * 4;
    const int h  = c >> 6;
    const int dd = c & 63;
    const float mu   = stats[(b * 16 + h) * 2 + 0];
    const float rstd = stats[(b * 16 + h) * 2 + 1];
    float4 v = *(const float4*)&y[(((size_t)(b * 16 + h)) * 1024 + t) * 64 + dd];
    float4 w = *(const float4*)&gw[c];
    float4 bb = *(const float4*)&gb[c];
    float f[4];
    f[0] = (v.x - mu) * rstd * w.x + bb.x;
    f[1] = (v.y - mu) * rstd * w.y + bb.y;
    f[2] = (v.z - mu) * rstd * w.z + bb.z;
    f[3] = (v.w - mu) * rstd * w.w + bb.w;
    __nv_bfloat16 hb[4], lb[4];
    #pragma unroll
    for (int j = 0; j < 4; j++) {
        hb[j] = __float2bfloat16_rn(f[j]);
        lb[j] = __float2bfloat16_rn(f[j] - __bfloat162float(hb[j]));
    }
    ((__nv_bfloat162*)hi)[2*i4 + 0] = __nv_bfloat162(hb[0], hb[1]);
    ((__nv_bfloat162*)hi)[2*i4 + 1] = __nv_bfloat162(hb[2], hb[3]);
    ((__nv_bfloat162*)lo)[2*i4 + 0] = __nv_bfloat162(lb[0], lb[1]);
    ((__nv_bfloat162*)lo)[2*i4 + 1] = __nv_bfloat162(lb[2], lb[3]);
}

// ===========================================================================
// Launch
// ===========================================================================
extern "C" void kernel_launch(void* const* d_in, const int* in_sizes, int n_in,
                              void* d_out, int out_size)
{
    const float* x_q  = (const float*)d_in[0];
    const float* x_kv = (const float*)d_in[1];
    const float* Wq   = (const float*)d_in[2];
    const float* Wkv  = (const float*)d_in[3];
    const float* Wc   = (const float*)d_in[4];
    const float* qn1  = (const float*)d_in[5];
    const float* kn1  = (const float*)d_in[6];
    const float* qn2  = (const float*)d_in[7];
    const float* kn2  = (const float*)d_in[8];
    const float* gn_w = (const float*)d_in[9];
    const float* gn_b = (const float*)d_in[10];
    const float* lmb  = (const float*)d_in[11];
    float* out = (float*)d_out;

    float *y, *stats;
    cudaGetSymbolAddress((void**)&y,      g_y);
    cudaGetSymbolAddress((void**)&stats,  g_stats);

    __nv_bfloat16 *xq_hi, *xq_lo, *xkv_hi, *xkv_lo;
    __nv_bfloat16 *wqt_hi, *wqt_lo, *wkvt_hi, *wkvt_lo, *wct_hi, *wct_lo;
    __nv_bfloat16 *ybt_hi, *ybt_lo;
    __nv_bfloat16 *q1h, *q1l, *q2h, *q2l, *k1h, *k1l, *k2h, *k2l, *vhh, *vhl;
    cudaGetSymbolAddress((void**)&xq_hi,   g_xq_hi);
    cudaGetSymbolAddress((void**)&xq_lo,   g_xq_lo);
    cudaGetSymbolAddress((void**)&xkv_hi,  g_xkv_hi);
    cudaGetSymbolAddress((void**)&xkv_lo,  g_xkv_lo);
    cudaGetSymbolAddress((void**)&wqt_hi,  g_wqt_hi);
    cudaGetSymbolAddress((void**)&wqt_lo,  g_wqt_lo);
    cudaGetSymbolAddress((void**)&wkvt_hi, g_wkvt_hi);
    cudaGetSymbolAddress((void**)&wkvt_lo, g_wkvt_lo);
    cudaGetSymbolAddress((void**)&wct_hi,  g_wct_hi);
    cudaGetSymbolAddress((void**)&wct_lo,  g_wct_lo);
    cudaGetSymbolAddress((void**)&ybt_hi,  g_ybt_hi);
    cudaGetSymbolAddress((void**)&ybt_lo,  g_ybt_lo);
    cudaGetSymbolAddress((void**)&q1h, g_q1h);
    cudaGetSymbolAddress((void**)&q1l, g_q1l);
    cudaGetSymbolAddress((void**)&q2h, g_q2h);
    cudaGetSymbolAddress((void**)&q2l, g_q2l);
    cudaGetSymbolAddress((void**)&k1h, g_k1h);
    cudaGetSymbolAddress((void**)&k1l, g_k1l);
    cudaGetSymbolAddress((void**)&k2h, g_k2h);
    cudaGetSymbolAddress((void**)&k2l, g_k2l);
    cudaGetSymbolAddress((void**)&vhh, g_vhh);
    cudaGetSymbolAddress((void**)&vhl, g_vhl);

    const int M = B_ * TQ_;  // 4096

    cudaFuncSetAttribute(gemm_mma, cudaFuncAttributeMaxDynamicSharedMemorySize, GM_SMEM);
    cudaFuncSetAttribute(gemm_mma_rms, cudaFuncAttributeMaxDynamicSharedMemorySize, GM_SMEM);
    cudaFuncSetAttribute(flash_mma_kernel, cudaFuncAttributeMaxDynamicSharedMemorySize, FLASH_SMEM);

    // 0) split/convert operands to bf16 hi/lo
    {
        const int n4 = M * D_ / 4;
        split_kernel<<<n4 / 256, 256>>>(x_q,  xq_hi,  xq_lo,  n4);
        split_kernel<<<n4 / 256, 256>>>(x_kv, xkv_hi, xkv_lo, n4);
        split_transpose_kernel<<<dim3(2 * D_ / 32, D_ / 32), dim3(32, 8)>>>(Wq,  wqt_hi,  wqt_lo,  D_, 2 * D_);
        split_transpose_kernel<<<dim3(3 * D_ / 32, D_ / 32), dim3(32, 8)>>>(Wkv, wkvt_hi, wkvt_lo, D_, 3 * D_);
        split_transpose_kernel<<<dim3(D_ / 32, D_ / 32),     dim3(32, 8)>>>(Wc,  wct_hi,  wct_lo,  D_, D_);
    }

    // 1) projections with fused RMSNorm + reshape + split (mma.sync bf16x3)
    {
        RmsDst Pq;
        Pq.w0 = qn1; Pq.w1 = qn2;
        Pq.h0 = q1h; Pq.l0 = q1l;
        Pq.h1 = q2h; Pq.l1 = q2l;
        Pq.h2 = nullptr; Pq.l2 = nullptr;
        Pq.qscale = 0.125f;
        gemm_mma_rms<<<dim3(2 * D_ / 128, M / 128), 256, GM_SMEM>>>(
            xq_hi, xq_lo, wqt_hi, wqt_lo, Pq, M, 2 * D_, D_);

        RmsDst Pkv;
        Pkv.w0 = kn1; Pkv.w1 = kn2;
        Pkv.h0 = k1h; Pkv.l0 = k1l;
        Pkv.h1 = k2h; Pkv.l1 = k2l;
        Pkv.h2 = vhh; Pkv.l2 = vhl;
        Pkv.qscale = 1.0f;
        gemm_mma_rms<<<dim3(3 * D_ / 128, M / 128), 256, GM_SMEM>>>(
            xkv_hi, xkv_lo, wkvt_hi, wkvt_lo, Pkv, M, 3 * D_, D_);
    }

    // 2) merged dual flash attention (mma.sync bf16x3, single kv pass)
    flash_mma_kernel<<<dim3(TQ_ / 128, H_, B_), 256, FLASH_SMEM>>>(
        q1h, q1l, q2h, q2l, k1h, k1l, k2h, k2l, vhh, vhl, lmb, y);

    // 3) GroupNorm
    gn_stats_kernel<<<B_ * H_, 256>>>(y, stats);
    gn_apply_kernel<<<(B_ * TQ_ * D_ / 4) / 256, 256>>>(y, stats, gn_w, gn_b, ybt_hi, ybt_lo);

    // 4) output projection (mma.sync bf16x3)
    gemm_mma<<<dim3(D_ / 128, M / 128), 256, GM_SMEM>>>(ybt_hi, ybt_lo, wct_hi, wct_lo, out, M, D_, D_);
}